// round 1
// baseline (speedup 1.0000x reference)
#include <cuda_runtime.h>
#include <math.h>

#define B_    4
#define L_    16384
#define D_    256
#define H_    8
#define DH_   32
#define FF_   1024
#define MTOK  65536      // B_*L_
#define NCH   16         // chunks for kv reduction
#define CHTOK 1024       // L_/NCH

// ---------------- scratch (static device globals; no allocation) ----------------
__device__ float g_q[MTOK * D_];
__device__ float g_k[MTOK * D_];
__device__ float g_v[MTOK * D_];
__device__ float g_x1[MTOK * D_];
__device__ float g_kvpart[NCH * 32 * 1024];  // [chunk][b*h][d*32+e]
__device__ float g_kspart[NCH * 32 * 32];    // [chunk][b*h][d]
__device__ float g_kv[32 * 1024];            // [b*h][d*32+e]
__device__ float g_ksum[32 * 32];            // [b*h][d]

// ============================================================================
// Kernel 1: fused QKV projection.  C[M,768] = X[M,256] @ [Wq|Wk|Wv], +bias,
// phi() applied for q and k.  Tiles: BM=64, BN=64, BK=32; 256 thr, 4x4/thread.
// ============================================================================
__global__ __launch_bounds__(256) void k_qkv(
    const float* __restrict__ x,
    const float* __restrict__ Wq, const float* __restrict__ bq,
    const float* __restrict__ Wk, const float* __restrict__ bk,
    const float* __restrict__ Wv, const float* __restrict__ bv)
{
    __shared__ float s_a[64 * 32];
    __shared__ float s_b[32 * 64];
    const int tid = threadIdx.x;
    const int m0  = blockIdx.y * 64;
    const int nb  = blockIdx.x;            // 0..11
    const int sel = nb >> 2;               // 0=q 1=k 2=v
    const int n0  = (nb & 3) * 64;

    const float* W    = (sel == 0) ? Wq : (sel == 1 ? Wk : Wv);
    const float* bias = (sel == 0) ? bq : (sel == 1 ? bk : bv);
    float* outp       = (sel == 0) ? g_q : (sel == 1 ? g_k : g_v);

    const int ty = tid >> 4;   // 0..15 -> rows ty*4..+3
    const int tx = tid & 15;   // 0..15 -> cols tx*4..+3

    float c[4][4];
#pragma unroll
    for (int i = 0; i < 4; i++)
#pragma unroll
        for (int j = 0; j < 4; j++) c[i][j] = 0.f;

    for (int kb = 0; kb < 8; kb++) {
#pragma unroll
        for (int t = 0; t < 2; t++) {
            int v4 = tid + t * 256;               // 0..511 float4 slots
            int row = v4 >> 3, k4 = v4 & 7;
            *(float4*)&s_a[row * 32 + k4 * 4] =
                *(const float4*)&x[(size_t)(m0 + row) * D_ + kb * 32 + k4 * 4];
        }
#pragma unroll
        for (int t = 0; t < 2; t++) {
            int v4 = tid + t * 256;
            int kk = v4 >> 4, j4 = v4 & 15;
            *(float4*)&s_b[kk * 64 + j4 * 4] =
                *(const float4*)&W[(size_t)(kb * 32 + kk) * D_ + n0 + j4 * 4];
        }
        __syncthreads();
#pragma unroll
        for (int k4 = 0; k4 < 8; k4++) {
            float a_s[4][4];
#pragma unroll
            for (int i = 0; i < 4; i++) {
                float4 t4 = *(float4*)&s_a[(ty * 4 + i) * 32 + k4 * 4];
                a_s[i][0] = t4.x; a_s[i][1] = t4.y; a_s[i][2] = t4.z; a_s[i][3] = t4.w;
            }
#pragma unroll
            for (int u = 0; u < 4; u++) {
                float4 b4 = *(float4*)&s_b[(k4 * 4 + u) * 64 + tx * 4];
#pragma unroll
                for (int i = 0; i < 4; i++) {
                    c[i][0] += a_s[i][u] * b4.x;
                    c[i][1] += a_s[i][u] * b4.y;
                    c[i][2] += a_s[i][u] * b4.z;
                    c[i][3] += a_s[i][u] * b4.w;
                }
            }
        }
        __syncthreads();
    }

    float4 bv4 = *(const float4*)&bias[n0 + tx * 4];
#pragma unroll
    for (int i = 0; i < 4; i++) {
        int row = m0 + ty * 4 + i;
        float o[4];
        o[0] = c[i][0] + bv4.x; o[1] = c[i][1] + bv4.y;
        o[2] = c[i][2] + bv4.z; o[3] = c[i][3] + bv4.w;
        if (sel < 2) {
#pragma unroll
            for (int j = 0; j < 4; j++)
                o[j] = (o[j] > 0.f) ? (o[j] + 1.f) : expf(o[j]);
        }
        float4 ov = make_float4(o[0], o[1], o[2], o[3]);
        *(float4*)&outp[(size_t)row * D_ + n0 + tx * 4] = ov;
    }
}

// ============================================================================
// Kernel 2: partial kv = sum_l phi(k) outer phi? (k already phi'd) x v, and
// k_sum, per (b,h,chunk).  Warp-level: lane owns column e; kv row d via shfl.
// Deterministic (ordered in-block reduction, partials to global).
// ============================================================================
__global__ __launch_bounds__(256) void k_kvred()
{
    __shared__ float s_part[8 * 1024];   // per-warp kv
    __shared__ float s_ksp[8 * 32];
    const int bh = blockIdx.x;           // 0..31
    const int b = bh >> 3, h = bh & 7;
    const int ch = blockIdx.y;           // 0..NCH-1
    const int w = threadIdx.x >> 5, lane = threadIdx.x & 31;

    float acc[32];
#pragma unroll
    for (int d = 0; d < 32; d++) acc[d] = 0.f;
    float ks = 0.f;

    const int t0 = ch * CHTOK;
    for (int i = w; i < CHTOK; i += 8) {
        size_t tok = (size_t)b * L_ + t0 + i;
        float kval = g_k[tok * D_ + h * DH_ + lane];
        float vval = g_v[tok * D_ + h * DH_ + lane];
        ks += kval;
#pragma unroll
        for (int d = 0; d < 32; d++) {
            float kd = __shfl_sync(0xffffffffu, kval, d);
            acc[d] += kd * vval;
        }
    }
#pragma unroll
    for (int d = 0; d < 32; d++) s_part[w * 1024 + d * 32 + lane] = acc[d];
    s_ksp[w * 32 + lane] = ks;
    __syncthreads();

    for (int j = threadIdx.x; j < 1024; j += 256) {
        float s = 0.f;
#pragma unroll
        for (int ww = 0; ww < 8; ww++) s += s_part[ww * 1024 + j];
        g_kvpart[((size_t)ch * 32 + bh) * 1024 + j] = s;
    }
    if (threadIdx.x < 32) {
        float s = 0.f;
#pragma unroll
        for (int ww = 0; ww < 8; ww++) s += s_ksp[ww * 32 + threadIdx.x];
        g_kspart[(ch * 32 + bh) * 32 + threadIdx.x] = s;
    }
}

// Kernel 2b: ordered final reduction of chunk partials.
__global__ __launch_bounds__(256) void k_kvfin()
{
    const int bh = blockIdx.x;
    for (int j = threadIdx.x; j < 1024; j += 256) {
        float s = 0.f;
#pragma unroll
        for (int c = 0; c < NCH; c++) s += g_kvpart[((size_t)c * 32 + bh) * 1024 + j];
        g_kv[bh * 1024 + j] = s;
    }
    if (threadIdx.x < 32) {
        float s = 0.f;
#pragma unroll
        for (int c = 0; c < NCH; c++) s += g_kspart[(c * 32 + bh) * 32 + threadIdx.x];
        g_ksum[bh * 32 + threadIdx.x] = s;
    }
}

// ============================================================================
// Kernel 3: attention readout + Wo + residual + LayerNorm1.  32 tokens/block.
// dyn smem: kv(8192) ks(256) z(256) q/w(8192) a(8192) = 25088 floats = 100352B
// ============================================================================
__global__ __launch_bounds__(256) void k_attn(
    const float* __restrict__ x,
    const float* __restrict__ Wo, const float* __restrict__ bo,
    const float* __restrict__ lng, const float* __restrict__ lnb)
{
    extern __shared__ float sm[];
    float* s_kv = sm;           // 8192
    float* s_ks = sm + 8192;    // 256
    float* s_z  = sm + 8448;    // 256
    float* s_q  = sm + 8704;    // 8192 (reused as Wo tile)
    float* s_a  = sm + 16896;   // 8192

    const int tid  = threadIdx.x;
    const int tok0 = blockIdx.x * 32;
    const int b    = tok0 >> 14;     // tok0 / L_

    for (int i = tid; i < 2048; i += 256)
        *(float4*)&s_kv[i * 4] = *(const float4*)&g_kv[b * 8192 + i * 4];
    if (tid < 64)
        *(float4*)&s_ks[tid * 4] = *(const float4*)&g_ksum[b * 256 + tid * 4];
    for (int i = tid; i < 2048; i += 256)
        *(float4*)&s_q[i * 4] = *(const float4*)&g_q[(size_t)tok0 * D_ + i * 4];
    __syncthreads();

    {   // z[r][h] = 1/(q_phi . k_sum + 1e-6)
        int r = tid & 31, h = tid >> 5;
        float s = 0.f;
#pragma unroll
        for (int d4 = 0; d4 < 8; d4++) {
            float4 q4 = *(float4*)&s_q[r * 256 + h * 32 + d4 * 4];
            float4 k4 = *(float4*)&s_ks[h * 32 + d4 * 4];
            s += q4.x * k4.x + q4.y * k4.y + q4.z * k4.z + q4.w * k4.w;
        }
        s_z[r * 8 + h] = 1.f / (s + 1e-6f);
    }
    __syncthreads();

    {   // a[r][h*32+e] = z * sum_d q[r][h,d] * kv[h][d][e]
        int h = tid >> 5, e = tid & 31;
        float kvc[32];
#pragma unroll
        for (int d = 0; d < 32; d++) kvc[d] = s_kv[(h * 32 + d) * 32 + e];
        for (int r = 0; r < 32; r++) {
            float acc = 0.f;
#pragma unroll
            for (int d4 = 0; d4 < 8; d4++) {
                float4 q4 = *(float4*)&s_q[r * 256 + h * 32 + d4 * 4];
                acc += q4.x * kvc[d4 * 4] + q4.y * kvc[d4 * 4 + 1]
                     + q4.z * kvc[d4 * 4 + 2] + q4.w * kvc[d4 * 4 + 3];
            }
            s_a[r * 256 + h * 32 + e] = acc * s_z[r * 8 + h];
        }
    }
    __syncthreads();

    // GEMM: y[32,256] = a @ Wo
    float* s_w = s_q;
    const int ty = tid >> 5, tx = tid & 31;
    float c[4][8];
#pragma unroll
    for (int i = 0; i < 4; i++)
#pragma unroll
        for (int j = 0; j < 8; j++) c[i][j] = 0.f;

    for (int kb = 0; kb < 8; kb++) {
        for (int i = tid; i < 2048; i += 256)
            *(float4*)&s_w[i * 4] = *(const float4*)&Wo[kb * 8192 + i * 4];
        __syncthreads();
#pragma unroll
        for (int k4 = 0; k4 < 8; k4++) {
            float a_s[4][4];
#pragma unroll
            for (int i = 0; i < 4; i++) {
                float4 t4 = *(float4*)&s_a[(ty * 4 + i) * 256 + kb * 32 + k4 * 4];
                a_s[i][0] = t4.x; a_s[i][1] = t4.y; a_s[i][2] = t4.z; a_s[i][3] = t4.w;
            }
#pragma unroll
            for (int u = 0; u < 4; u++) {
                float4 w0 = *(float4*)&s_w[(k4 * 4 + u) * 256 + tx * 8];
                float4 w1 = *(float4*)&s_w[(k4 * 4 + u) * 256 + tx * 8 + 4];
#pragma unroll
                for (int i = 0; i < 4; i++) {
                    c[i][0] += a_s[i][u] * w0.x; c[i][1] += a_s[i][u] * w0.y;
                    c[i][2] += a_s[i][u] * w0.z; c[i][3] += a_s[i][u] * w0.w;
                    c[i][4] += a_s[i][u] * w1.x; c[i][5] += a_s[i][u] * w1.y;
                    c[i][6] += a_s[i][u] * w1.z; c[i][7] += a_s[i][u] * w1.w;
                }
            }
        }
        __syncthreads();
    }

    // epilogue: + bo + residual x  -> s_a, then LayerNorm1 -> g_x1
    float4 bo0 = *(const float4*)&bo[tx * 8];
    float4 bo1 = *(const float4*)&bo[tx * 8 + 4];
#pragma unroll
    for (int i = 0; i < 4; i++) {
        int row = ty * 4 + i;
        float4 x0 = *(const float4*)&x[(size_t)(tok0 + row) * D_ + tx * 8];
        float4 x1v = *(const float4*)&x[(size_t)(tok0 + row) * D_ + tx * 8 + 4];
        s_a[row * 256 + tx * 8 + 0] = c[i][0] + bo0.x + x0.x;
        s_a[row * 256 + tx * 8 + 1] = c[i][1] + bo0.y + x0.y;
        s_a[row * 256 + tx * 8 + 2] = c[i][2] + bo0.z + x0.z;
        s_a[row * 256 + tx * 8 + 3] = c[i][3] + bo0.w + x0.w;
        s_a[row * 256 + tx * 8 + 4] = c[i][4] + bo1.x + x1v.x;
        s_a[row * 256 + tx * 8 + 5] = c[i][5] + bo1.y + x1v.y;
        s_a[row * 256 + tx * 8 + 6] = c[i][6] + bo1.z + x1v.z;
        s_a[row * 256 + tx * 8 + 7] = c[i][7] + bo1.w + x1v.w;
    }
    __syncthreads();

    const int w = tid >> 5, lane = tid & 31;
#pragma unroll
    for (int rr = 0; rr < 4; rr++) {
        int row = w * 4 + rr;
        float vals[8];
        float sum = 0.f, sq = 0.f;
#pragma unroll
        for (int i = 0; i < 8; i++) {
            float v = s_a[row * 256 + lane + i * 32];
            vals[i] = v; sum += v; sq += v * v;
        }
#pragma unroll
        for (int off = 16; off > 0; off >>= 1) {
            sum += __shfl_xor_sync(0xffffffffu, sum, off);
            sq  += __shfl_xor_sync(0xffffffffu, sq,  off);
        }
        float mu  = sum * (1.f / 256.f);
        float var = sq * (1.f / 256.f) - mu * mu;
        float rs  = rsqrtf(var + 1e-5f);
#pragma unroll
        for (int i = 0; i < 8; i++) {
            int col = lane + i * 32;
            g_x1[(size_t)(tok0 + row) * D_ + col] =
                (vals[i] - mu) * rs * lng[col] + lnb[col];
        }
    }
}

// ============================================================================
// Kernel 4: FFN (relu(x1@W1+b1)@W2+b2) + residual + LayerNorm2 -> out.
// Hidden streamed in 64-wide chunks; never hits HBM.  32 tokens/block.
// dyn smem: x(8192) h(2048) w(8192) = 18432 floats = 73728B
// ============================================================================
__global__ __launch_bounds__(256) void k_ffn(
    const float* __restrict__ W1, const float* __restrict__ b1,
    const float* __restrict__ W2, const float* __restrict__ b2,
    const float* __restrict__ lng, const float* __restrict__ lnb,
    float* __restrict__ out)
{
    extern __shared__ float sm[];
    float* s_x = sm;            // 8192
    float* s_h = sm + 8192;     // 2048
    float* s_w = sm + 10240;    // 8192 (W1 tile / W2 tile / y staging)

    const int tid  = threadIdx.x;
    const int tok0 = blockIdx.x * 32;

    for (int i = tid; i < 2048; i += 256)
        *(float4*)&s_x[i * 4] = *(const float4*)&g_x1[(size_t)tok0 * D_ + i * 4];
    __syncthreads();

    const int ty = tid >> 5, tx = tid & 31;
    float c[4][8];
#pragma unroll
    for (int i = 0; i < 4; i++)
#pragma unroll
        for (int j = 0; j < 8; j++) c[i][j] = 0.f;

    for (int jc = 0; jc < 16; jc++) {
        // ---- GEMM1 chunk: h[32,64] = relu(s_x @ W1[:, jc*64 : jc*64+64] + b1)
        float hacc[4][2];
#pragma unroll
        for (int i = 0; i < 4; i++) { hacc[i][0] = 0.f; hacc[i][1] = 0.f; }

        for (int kb = 0; kb < 8; kb++) {
#pragma unroll
            for (int t = 0; t < 2; t++) {
                int v4 = tid + t * 256;
                int kk = v4 >> 4, j4 = v4 & 15;
                *(float4*)&s_w[kk * 64 + j4 * 4] =
                    *(const float4*)&W1[(size_t)(kb * 32 + kk) * FF_ + jc * 64 + j4 * 4];
            }
            __syncthreads();
#pragma unroll
            for (int k4 = 0; k4 < 8; k4++) {
                float a_s[4][4];
#pragma unroll
                for (int i = 0; i < 4; i++) {
                    float4 t4 = *(float4*)&s_x[(ty * 4 + i) * 256 + kb * 32 + k4 * 4];
                    a_s[i][0] = t4.x; a_s[i][1] = t4.y; a_s[i][2] = t4.z; a_s[i][3] = t4.w;
                }
#pragma unroll
                for (int u = 0; u < 4; u++) {
                    float2 wv = *(float2*)&s_w[(k4 * 4 + u) * 64 + tx * 2];
#pragma unroll
                    for (int i = 0; i < 4; i++) {
                        hacc[i][0] += a_s[i][u] * wv.x;
                        hacc[i][1] += a_s[i][u] * wv.y;
                    }
                }
            }
            __syncthreads();
        }
        float bb0 = b1[jc * 64 + tx * 2];
        float bb1 = b1[jc * 64 + tx * 2 + 1];
#pragma unroll
        for (int i = 0; i < 4; i++) {
            s_h[(ty * 4 + i) * 64 + tx * 2]     = fmaxf(hacc[i][0] + bb0, 0.f);
            s_h[(ty * 4 + i) * 64 + tx * 2 + 1] = fmaxf(hacc[i][1] + bb1, 0.f);
        }
        __syncthreads();

        // ---- GEMM2 chunk: c += h[32,64] @ W2[jc*64 : jc*64+64, :]
        for (int sub = 0; sub < 2; sub++) {
            for (int i = tid; i < 2048; i += 256)
                *(float4*)&s_w[i * 4] =
                    *(const float4*)&W2[(size_t)(jc * 64 + sub * 32) * D_ + i * 4];
            __syncthreads();
#pragma unroll
            for (int k4 = 0; k4 < 8; k4++) {
                float h_s[4][4];
#pragma unroll
                for (int i = 0; i < 4; i++) {
                    float4 t4 = *(float4*)&s_h[(ty * 4 + i) * 64 + sub * 32 + k4 * 4];
                    h_s[i][0] = t4.x; h_s[i][1] = t4.y; h_s[i][2] = t4.z; h_s[i][3] = t4.w;
                }
#pragma unroll
                for (int u = 0; u < 4; u++) {
                    float4 w0 = *(float4*)&s_w[(k4 * 4 + u) * 256 + tx * 8];
                    float4 w1 = *(float4*)&s_w[(k4 * 4 + u) * 256 + tx * 8 + 4];
#pragma unroll
                    for (int i = 0; i < 4; i++) {
                        c[i][0] += h_s[i][u] * w0.x; c[i][1] += h_s[i][u] * w0.y;
                        c[i][2] += h_s[i][u] * w0.z; c[i][3] += h_s[i][u] * w0.w;
                        c[i][4] += h_s[i][u] * w1.x; c[i][5] += h_s[i][u] * w1.y;
                        c[i][6] += h_s[i][u] * w1.z; c[i][7] += h_s[i][u] * w1.w;
                    }
                }
            }
            __syncthreads();
        }
    }

    // epilogue: y = c + b2 + x1  -> s_w, then LayerNorm2 -> out
    float4 b20 = *(const float4*)&b2[tx * 8];
    float4 b21 = *(const float4*)&b2[tx * 8 + 4];
#pragma unroll
    for (int i = 0; i < 4; i++) {
        int row = ty * 4 + i;
        float4 xv0 = *(float4*)&s_x[row * 256 + tx * 8];
        float4 xv1 = *(float4*)&s_x[row * 256 + tx * 8 + 4];
        s_w[row * 256 + tx * 8 + 0] = c[i][0] + b20.x + xv0.x;
        s_w[row * 256 + tx * 8 + 1] = c[i][1] + b20.y + xv0.y;
        s_w[row * 256 + tx * 8 + 2] = c[i][2] + b20.z + xv0.z;
        s_w[row * 256 + tx * 8 + 3] = c[i][3] + b20.w + xv0.w;
        s_w[row * 256 + tx * 8 + 4] = c[i][4] + b21.x + xv1.x;
        s_w[row * 256 + tx * 8 + 5] = c[i][5] + b21.y + xv1.y;
        s_w[row * 256 + tx * 8 + 6] = c[i][6] + b21.z + xv1.z;
        s_w[row * 256 + tx * 8 + 7] = c[i][7] + b21.w + xv1.w;
    }
    __syncthreads();

    const int w = tid >> 5, lane = tid & 31;
#pragma unroll
    for (int rr = 0; rr < 4; rr++) {
        int row = w * 4 + rr;
        float vals[8];
        float sum = 0.f, sq = 0.f;
#pragma unroll
        for (int i = 0; i < 8; i++) {
            float v = s_w[row * 256 + lane + i * 32];
            vals[i] = v; sum += v; sq += v * v;
        }
#pragma unroll
        for (int off = 16; off > 0; off >>= 1) {
            sum += __shfl_xor_sync(0xffffffffu, sum, off);
            sq  += __shfl_xor_sync(0xffffffffu, sq,  off);
        }
        float mu  = sum * (1.f / 256.f);
        float var = sq * (1.f / 256.f) - mu * mu;
        float rs  = rsqrtf(var + 1e-5f);
#pragma unroll
        for (int i = 0; i < 8; i++) {
            int col = lane + i * 32;
            out[(size_t)(tok0 + row) * D_ + col] =
                (vals[i] - mu) * rs * lng[col] + lnb[col];
        }
    }
}

// ============================================================================
extern "C" void kernel_launch(void* const* d_in, const int* in_sizes, int n_in,
                              void* d_out, int out_size)
{
    const float* x    = (const float*)d_in[0];
    const float* Wq   = (const float*)d_in[1];
    const float* bq   = (const float*)d_in[2];
    const float* Wk   = (const float*)d_in[3];
    const float* bk   = (const float*)d_in[4];
    const float* Wv   = (const float*)d_in[5];
    const float* bv   = (const float*)d_in[6];
    const float* Wo   = (const float*)d_in[7];
    const float* bo   = (const float*)d_in[8];
    const float* W1   = (const float*)d_in[9];
    const float* b1   = (const float*)d_in[10];
    const float* W2   = (const float*)d_in[11];
    const float* b2   = (const float*)d_in[12];
    const float* ln1g = (const float*)d_in[13];
    const float* ln1b = (const float*)d_in[14];
    const float* ln2g = (const float*)d_in[15];
    const float* ln2b = (const float*)d_in[16];
    float* out = (float*)d_out;

    cudaFuncSetAttribute(k_attn, cudaFuncAttributeMaxDynamicSharedMemorySize, 100352);
    cudaFuncSetAttribute(k_ffn,  cudaFuncAttributeMaxDynamicSharedMemorySize, 73728);

    k_qkv<<<dim3(12, MTOK / 64), 256>>>(x, Wq, bq, Wk, bk, Wv, bv);
    k_kvred<<<dim3(32, NCH), 256>>>();
    k_kvfin<<<32, 256>>>();
    k_attn<<<MTOK / 32, 256, 100352>>>(x, Wo, bo, ln1g, ln1b);
    k_ffn<<<MTOK / 32, 256, 73728>>>(W1, b1, W2, b2, ln2g, ln2b, out);
}

// round 3
// speedup vs baseline: 3.0071x; 3.0071x over previous
#include <cuda_runtime.h>
#include <math.h>
#include <stdint.h>

#define B_    4
#define L_    16384
#define D_    256
#define H_    8
#define DH_   32
#define FF_   1024
#define MTOK  65536
#define NCH   16
#define CHTOK 1024

// ---------------- scratch ----------------
__device__ float g_q [MTOK * D_];
__device__ float g_k [MTOK * D_];
__device__ float g_v [MTOK * D_];
__device__ float g_a [MTOK * D_];
__device__ float g_y [MTOK * D_];
__device__ float g_x1[MTOK * D_];
__device__ float g_h [MTOK * FF_];
__device__ float g_kvpart[NCH * 32 * 1024];
__device__ float g_kspart[NCH * 32 * 32];
__device__ float g_kv[32 * 1024];
__device__ float g_ksum[32 * 32];
// transposed weights [N,K] row-major
__device__ float g_wqT[D_ * D_];
__device__ float g_wkT[D_ * D_];
__device__ float g_wvT[D_ * D_];
__device__ float g_woT[D_ * D_];
__device__ float g_w1T[FF_ * D_];
__device__ float g_w2T[D_ * FF_];

// ---------------- helpers ----------------
__device__ __forceinline__ uint32_t smem_u32(const void* p) {
    uint32_t a;
    asm("{ .reg .u64 t; cvta.to.shared.u64 t, %1; cvt.u32.u64 %0, t; }" : "=r"(a) : "l"(p));
    return a;
}
__device__ __forceinline__ void cp16(uint32_t dst, const void* src) {
    asm volatile("cp.async.cg.shared.global [%0], [%1], 16;" :: "r"(dst), "l"(src));
}
__device__ __forceinline__ uint32_t f2tf(float f) {
    uint32_t r; asm("cvt.rna.tf32.f32 %0, %1;" : "=r"(r) : "f"(f)); return r;
}
__device__ __forceinline__ void mma8(float* c, const uint32_t* a, const uint32_t* b) {
    asm volatile("mma.sync.aligned.m16n8k8.row.col.f32.tf32.tf32.f32 "
        "{%0,%1,%2,%3}, {%4,%5,%6,%7}, {%8,%9}, {%0,%1,%2,%3};"
        : "+f"(c[0]), "+f"(c[1]), "+f"(c[2]), "+f"(c[3])
        : "r"(a[0]), "r"(a[1]), "r"(a[2]), "r"(a[3]), "r"(b[0]), "r"(b[1]));
}

// ============================================================================
// Weight transpose Wt[n][k] = W[k][n]
// ============================================================================
__global__ void k_tr(const float* __restrict__ W, float* __restrict__ Wt, int K, int N)
{
    __shared__ float t[32][33];
    int n0 = blockIdx.x * 32, k0 = blockIdx.y * 32;
    int x = threadIdx.x, y = threadIdx.y;
    for (int i = y; i < 32; i += 8) t[i][x] = W[(size_t)(k0 + i) * N + n0 + x];
    __syncthreads();
    for (int i = y; i < 32; i += 8) Wt[(size_t)(n0 + i) * K + k0 + x] = t[x][i];
}

// ============================================================================
// tf32 mma.sync GEMM: Out[m0..+128, n0..+128] = A[128,K] @ Bt[N,K]^T + bias
// ACT: 0 none, 1 phi (elu+1), 2 relu.
// smem: double-buffered A/B tiles 128x32 padded to 36 floats/row.
// ============================================================================
__device__ __forceinline__ void stage(const float* __restrict__ Ap,
                                      const float* __restrict__ Bp,
                                      int K, uint32_t sa, uint32_t sb, int tid)
{
#pragma unroll
    for (int t = 0; t < 4; t++) {
        int i = tid + t * 256;
        int row = i >> 3, c4 = i & 7;
        cp16(sa + row * 144 + c4 * 16, Ap + (size_t)row * K + c4 * 4);
    }
#pragma unroll
    for (int t = 0; t < 4; t++) {
        int i = tid + t * 256;
        int row = i >> 3, c4 = i & 7;
        cp16(sb + row * 144 + c4 * 16, Bp + (size_t)row * K + c4 * 4);
    }
}

template <int ACT>
__global__ __launch_bounds__(256, 2) void k_gemm(
    const float* __restrict__ A, const float* __restrict__ Bt,
    const float* __restrict__ bias, float* __restrict__ Out,
    int K, int Nout)
{
    extern __shared__ float sm[];
    float* sAb[2] = { sm,        sm + 4608 };
    float* sBb[2] = { sm + 9216, sm + 13824 };

    const int tid  = threadIdx.x;
    const int wid  = tid >> 5;
    const int lane = tid & 31;
    const int g = lane >> 2, t = lane & 3;
    const int wm = wid & 3, wn = wid >> 2;
    const int m0 = blockIdx.y * 128;
    const int n0 = blockIdx.x * 128;
    const int NC = K >> 5;

    uint32_t uA[2], uB[2];
    uA[0] = smem_u32(sAb[0]); uA[1] = smem_u32(sAb[1]);
    uB[0] = smem_u32(sBb[0]); uB[1] = smem_u32(sBb[1]);

    float c[2][8][4] = {};

    stage(A + (size_t)m0 * K, Bt + (size_t)n0 * K, K, uA[0], uB[0], tid);
    asm volatile("cp.async.commit_group;");

    for (int cc = 0; cc < NC; cc++) {
        const int cur = cc & 1;
        if (cc + 1 < NC) {
            stage(A + (size_t)m0 * K + (cc + 1) * 32,
                  Bt + (size_t)n0 * K + (cc + 1) * 32, K,
                  uA[cur ^ 1], uB[cur ^ 1], tid);
            asm volatile("cp.async.commit_group;");
            asm volatile("cp.async.wait_group 1;");
        } else {
            asm volatile("cp.async.wait_group 0;");
        }
        __syncthreads();

        const float* a_s = sAb[cur];
        const float* b_s = sBb[cur];
#pragma unroll
        for (int s = 0; s < 4; s++) {
            uint32_t af[2][4], bf[8][2];
#pragma unroll
            for (int i = 0; i < 2; i++) {
                const int rb = (2 * wm + i) * 16;
                af[i][0] = f2tf(a_s[(rb + g)     * 36 + s * 8 + t]);
                af[i][1] = f2tf(a_s[(rb + g + 8) * 36 + s * 8 + t]);
                af[i][2] = f2tf(a_s[(rb + g)     * 36 + s * 8 + t + 4]);
                af[i][3] = f2tf(a_s[(rb + g + 8) * 36 + s * 8 + t + 4]);
            }
#pragma unroll
            for (int j = 0; j < 8; j++) {
                const int n = (wn * 8 + j) * 8 + g;
                bf[j][0] = f2tf(b_s[n * 36 + s * 8 + t]);
                bf[j][1] = f2tf(b_s[n * 36 + s * 8 + t + 4]);
            }
#pragma unroll
            for (int i = 0; i < 2; i++)
#pragma unroll
                for (int j = 0; j < 8; j++)
                    mma8(c[i][j], af[i], bf[j]);
        }
        __syncthreads();
    }

    // epilogue: bias + activation, direct float2 stores
#pragma unroll
    for (int j = 0; j < 8; j++) {
        const int col = n0 + (wn * 8 + j) * 8 + t * 2;
        const float b0 = __ldg(&bias[col]);
        const float b1 = __ldg(&bias[col + 1]);
#pragma unroll
        for (int i = 0; i < 2; i++) {
            const int r0 = m0 + (2 * wm + i) * 16 + g;
            float v0 = c[i][j][0] + b0, v1 = c[i][j][1] + b1;
            float v2 = c[i][j][2] + b0, v3 = c[i][j][3] + b1;
            if (ACT == 1) {
                v0 = (v0 > 0.f) ? (v0 + 1.f) : expf(v0);
                v1 = (v1 > 0.f) ? (v1 + 1.f) : expf(v1);
                v2 = (v2 > 0.f) ? (v2 + 1.f) : expf(v2);
                v3 = (v3 > 0.f) ? (v3 + 1.f) : expf(v3);
            }
            if (ACT == 2) {
                v0 = fmaxf(v0, 0.f); v1 = fmaxf(v1, 0.f);
                v2 = fmaxf(v2, 0.f); v3 = fmaxf(v3, 0.f);
            }
            *(float2*)&Out[(size_t)r0 * Nout + col]       = make_float2(v0, v1);
            *(float2*)&Out[(size_t)(r0 + 8) * Nout + col] = make_float2(v2, v3);
        }
    }
}

// ============================================================================
// kv reduction
// ============================================================================
__global__ __launch_bounds__(256) void k_kvred()
{
    __shared__ float s_part[8 * 1024];
    __shared__ float s_ksp[8 * 32];
    const int bh = blockIdx.x;
    const int b = bh >> 3, h = bh & 7;
    const int ch = blockIdx.y;
    const int w = threadIdx.x >> 5, lane = threadIdx.x & 31;

    float acc[32];
#pragma unroll
    for (int d = 0; d < 32; d++) acc[d] = 0.f;
    float ks = 0.f;
    const int t0 = ch * CHTOK;
    for (int i = w; i < CHTOK; i += 8) {
        size_t tok = (size_t)b * L_ + t0 + i;
        float kval = g_k[tok * D_ + h * DH_ + lane];
        float vval = g_v[tok * D_ + h * DH_ + lane];
        ks += kval;
#pragma unroll
        for (int d = 0; d < 32; d++) {
            float kd = __shfl_sync(0xffffffffu, kval, d);
            acc[d] += kd * vval;
        }
    }
#pragma unroll
    for (int d = 0; d < 32; d++) s_part[w * 1024 + d * 32 + lane] = acc[d];
    s_ksp[w * 32 + lane] = ks;
    __syncthreads();
    for (int j = threadIdx.x; j < 1024; j += 256) {
        float s = 0.f;
#pragma unroll
        for (int ww = 0; ww < 8; ww++) s += s_part[ww * 1024 + j];
        g_kvpart[((size_t)ch * 32 + bh) * 1024 + j] = s;
    }
    if (threadIdx.x < 32) {
        float s = 0.f;
#pragma unroll
        for (int ww = 0; ww < 8; ww++) s += s_ksp[ww * 32 + threadIdx.x];
        g_kspart[(ch * 32 + bh) * 32 + threadIdx.x] = s;
    }
}

__global__ __launch_bounds__(256) void k_kvfin()
{
    const int bh = blockIdx.x;
    for (int j = threadIdx.x; j < 1024; j += 256) {
        float s = 0.f;
#pragma unroll
        for (int c = 0; c < NCH; c++) s += g_kvpart[((size_t)c * 32 + bh) * 1024 + j];
        g_kv[bh * 1024 + j] = s;
    }
    if (threadIdx.x < 32) {
        float s = 0.f;
#pragma unroll
        for (int c = 0; c < NCH; c++) s += g_kspart[(c * 32 + bh) * 32 + threadIdx.x];
        g_ksum[bh * 32 + threadIdx.x] = s;
    }
}

// ============================================================================
// attention readout
// ============================================================================
__global__ __launch_bounds__(256) void k_attnread(float* __restrict__ outa)
{
    extern __shared__ float smr[];
    float* s_kv = smr;
    float* s_ks = smr + 8192;
    float* s_z  = smr + 8448;
    float* s_q  = smr + 8704;

    const int tid  = threadIdx.x;
    const int tok0 = blockIdx.x * 32;
    const int b    = tok0 >> 14;

    for (int i = tid; i < 2048; i += 256)
        *(float4*)&s_kv[i * 4] = *(const float4*)&g_kv[b * 8192 + i * 4];
    if (tid < 64)
        *(float4*)&s_ks[tid * 4] = *(const float4*)&g_ksum[b * 256 + tid * 4];
    for (int i = tid; i < 2048; i += 256)
        *(float4*)&s_q[i * 4] = *(const float4*)&g_q[(size_t)tok0 * D_ + i * 4];
    __syncthreads();

    {
        int r = tid & 31, h = tid >> 5;
        float s = 0.f;
#pragma unroll
        for (int d4 = 0; d4 < 8; d4++) {
            float4 q4 = *(float4*)&s_q[r * 256 + h * 32 + d4 * 4];
            float4 k4 = *(float4*)&s_ks[h * 32 + d4 * 4];
            s += q4.x * k4.x + q4.y * k4.y + q4.z * k4.z + q4.w * k4.w;
        }
        s_z[r * 8 + h] = 1.f / (s + 1e-6f);
    }
    __syncthreads();

    {
        int h = tid >> 5, e = tid & 31;
        float kvc[32];
#pragma unroll
        for (int d = 0; d < 32; d++) kvc[d] = s_kv[(h * 32 + d) * 32 + e];
        for (int r = 0; r < 32; r++) {
            float acc = 0.f;
#pragma unroll
            for (int d4 = 0; d4 < 8; d4++) {
                float4 q4 = *(float4*)&s_q[r * 256 + h * 32 + d4 * 4];
                acc += q4.x * kvc[d4 * 4] + q4.y * kvc[d4 * 4 + 1]
                     + q4.z * kvc[d4 * 4 + 2] + q4.w * kvc[d4 * 4 + 3];
            }
            outa[(size_t)(tok0 + r) * D_ + tid] = acc * s_z[r * 8 + h];
        }
    }
}

// ============================================================================
// residual + LayerNorm
// ============================================================================
__global__ __launch_bounds__(256) void k_resln(
    const float* __restrict__ ain, const float* __restrict__ bin,
    const float* __restrict__ g, const float* __restrict__ be,
    float* __restrict__ o)
{
    const int tid = threadIdx.x;
    const int tok0 = blockIdx.x * 32;
    const int w = tid >> 5, lane = tid & 31;
#pragma unroll
    for (int rr = 0; rr < 4; rr++) {
        int row = w * 4 + rr;
        size_t rb = (size_t)(tok0 + row) * D_;
        float vals[8];
        float sum = 0.f, sq = 0.f;
#pragma unroll
        for (int i = 0; i < 8; i++) {
            float v = ain[rb + lane + i * 32] + bin[rb + lane + i * 32];
            vals[i] = v; sum += v; sq += v * v;
        }
#pragma unroll
        for (int off = 16; off > 0; off >>= 1) {
            sum += __shfl_xor_sync(0xffffffffu, sum, off);
            sq  += __shfl_xor_sync(0xffffffffu, sq,  off);
        }
        float mu  = sum * (1.f / 256.f);
        float var = sq * (1.f / 256.f) - mu * mu;
        float rs  = rsqrtf(var + 1e-5f);
#pragma unroll
        for (int i = 0; i < 8; i++) {
            int col = lane + i * 32;
            o[rb + col] = (vals[i] - mu) * rs * g[col] + be[col];
        }
    }
}

// ============================================================================
extern "C" void kernel_launch(void* const* d_in, const int* in_sizes, int n_in,
                              void* d_out, int out_size)
{
    const float* x    = (const float*)d_in[0];
    const float* Wq   = (const float*)d_in[1];
    const float* bq   = (const float*)d_in[2];
    const float* Wk   = (const float*)d_in[3];
    const float* bk   = (const float*)d_in[4];
    const float* Wv   = (const float*)d_in[5];
    const float* bv   = (const float*)d_in[6];
    const float* Wo   = (const float*)d_in[7];
    const float* bo   = (const float*)d_in[8];
    const float* W1   = (const float*)d_in[9];
    const float* b1   = (const float*)d_in[10];
    const float* W2   = (const float*)d_in[11];
    const float* b2   = (const float*)d_in[12];
    const float* ln1g = (const float*)d_in[13];
    const float* ln1b = (const float*)d_in[14];
    const float* ln2g = (const float*)d_in[15];
    const float* ln2b = (const float*)d_in[16];
    float* out = (float*)d_out;

    float *wqT, *wkT, *wvT, *woT, *w1T, *w2T;
    float *q, *k, *v, *a, *y, *x1, *h;
    cudaGetSymbolAddress((void**)&wqT, g_wqT);
    cudaGetSymbolAddress((void**)&wkT, g_wkT);
    cudaGetSymbolAddress((void**)&wvT, g_wvT);
    cudaGetSymbolAddress((void**)&woT, g_woT);
    cudaGetSymbolAddress((void**)&w1T, g_w1T);
    cudaGetSymbolAddress((void**)&w2T, g_w2T);
    cudaGetSymbolAddress((void**)&q,  g_q);
    cudaGetSymbolAddress((void**)&k,  g_k);
    cudaGetSymbolAddress((void**)&v,  g_v);
    cudaGetSymbolAddress((void**)&a,  g_a);
    cudaGetSymbolAddress((void**)&y,  g_y);
    cudaGetSymbolAddress((void**)&x1, g_x1);
    cudaGetSymbolAddress((void**)&h,  g_h);

    const int GSM = 73728;
    cudaFuncSetAttribute(k_gemm<0>, cudaFuncAttributeMaxDynamicSharedMemorySize, GSM);
    cudaFuncSetAttribute(k_gemm<1>, cudaFuncAttributeMaxDynamicSharedMemorySize, GSM);
    cudaFuncSetAttribute(k_gemm<2>, cudaFuncAttributeMaxDynamicSharedMemorySize, GSM);
    cudaFuncSetAttribute(k_attnread, cudaFuncAttributeMaxDynamicSharedMemorySize, 67584);

    dim3 trb(32, 8);
    k_tr<<<dim3(8, 8),  trb>>>(Wq, wqT, D_, D_);
    k_tr<<<dim3(8, 8),  trb>>>(Wk, wkT, D_, D_);
    k_tr<<<dim3(8, 8),  trb>>>(Wv, wvT, D_, D_);
    k_tr<<<dim3(8, 8),  trb>>>(Wo, woT, D_, D_);
    k_tr<<<dim3(32, 8), trb>>>(W1, w1T, D_, FF_);
    k_tr<<<dim3(8, 32), trb>>>(W2, w2T, FF_, D_);

    // QKV projections (phi fused for q,k)
    k_gemm<1><<<dim3(2, 512), 256, GSM>>>(x, wqT, bq, q, D_, D_);
    k_gemm<1><<<dim3(2, 512), 256, GSM>>>(x, wkT, bk, k, D_, D_);
    k_gemm<0><<<dim3(2, 512), 256, GSM>>>(x, wvT, bv, v, D_, D_);

    k_kvred<<<dim3(32, NCH), 256>>>();
    k_kvfin<<<32, 256>>>();
    k_attnread<<<MTOK / 32, 256, 67584>>>(a);

    // Wo projection + residual/LN1
    k_gemm<0><<<dim3(2, 512), 256, GSM>>>(a, woT, bo, y, D_, D_);
    k_resln<<<MTOK / 32, 256>>>(x, y, ln1g, ln1b, x1);

    // FFN
    k_gemm<2><<<dim3(8, 512), 256, GSM>>>(x1, w1T, b1, h, D_, FF_);
    k_gemm<0><<<dim3(2, 512), 256, GSM>>>(h, w2T, b2, y, FF_, D_);
    k_resln<<<MTOK / 32, 256>>>(x1, y, ln2g, ln2b, out);
}

// round 4
// speedup vs baseline: 3.4724x; 1.1547x over previous
#include <cuda_runtime.h>
#include <math.h>
#include <stdint.h>

#define B_    4
#define L_    16384
#define D_    256
#define H_    8
#define DH_   32
#define FF_   1024
#define MTOK  65536
#define NCH   16
#define CHTOK 1024

// ---------------- scratch ----------------
__device__ float g_xr [MTOK * D_];       // x rounded to tf32
__device__ float g_qkv[MTOK * 768];      // q|k|v per token
__device__ float g_a  [MTOK * D_];       // attn readout (tf32-rounded)
__device__ float g_y  [MTOK * D_];
__device__ float g_x1 [MTOK * D_];
__device__ float g_x1r[MTOK * D_];       // x1 rounded to tf32
__device__ float g_h  [MTOK * FF_];      // hidden (tf32-rounded)
__device__ float g_kvpart[NCH * 32 * 1024];
__device__ float g_kspart[NCH * 32 * 32];
__device__ float g_kv[32 * 1024];
__device__ float g_ksum[32 * 32];
// transposed weights [N,K] row-major, tf32-rounded
__device__ float g_wqkvT[768 * D_];
__device__ float g_woT[D_ * D_];
__device__ float g_w1T[FF_ * D_];
__device__ float g_w2T[D_ * FF_];
__device__ float g_bqkv[768];

// ---------------- helpers ----------------
__device__ __forceinline__ uint32_t smem_u32(const void* p) {
    uint32_t a;
    asm("{ .reg .u64 t; cvta.to.shared.u64 t, %1; cvt.u32.u64 %0, t; }" : "=r"(a) : "l"(p));
    return a;
}
__device__ __forceinline__ void cp16(uint32_t dst, const void* src) {
    asm volatile("cp.async.cg.shared.global [%0], [%1], 16;" :: "r"(dst), "l"(src));
}
__device__ __forceinline__ float rtf(float f) {   // round-to-nearest tf32, as float
    uint32_t r; asm("cvt.rna.tf32.f32 %0, %1;" : "=r"(r) : "f"(f));
    return __uint_as_float(r);
}
__device__ __forceinline__ void mma8(float* c, const float2 a0, const float2 a1,
                                     const float2 b) {
    asm volatile("mma.sync.aligned.m16n8k8.row.col.f32.tf32.tf32.f32 "
        "{%0,%1,%2,%3}, {%4,%5,%6,%7}, {%8,%9}, {%0,%1,%2,%3};"
        : "+f"(c[0]), "+f"(c[1]), "+f"(c[2]), "+f"(c[3])
        : "r"(__float_as_uint(a0.x)), "r"(__float_as_uint(a1.x)),
          "r"(__float_as_uint(a0.y)), "r"(__float_as_uint(a1.y)),
          "r"(__float_as_uint(b.x)),  "r"(__float_as_uint(b.y)));
}

// ============================================================================
// x -> tf32-rounded copy
// ============================================================================
__global__ __launch_bounds__(512) void k_roundx(const float* __restrict__ x)
{
    int i = blockIdx.x * 512 + threadIdx.x;       // one float4 each
    float4 v = *(const float4*)&x[(size_t)i * 4];
    v.x = rtf(v.x); v.y = rtf(v.y); v.z = rtf(v.z); v.w = rtf(v.w);
    *(float4*)&g_xr[(size_t)i * 4] = v;
}

__global__ void k_catb(const float* __restrict__ bq, const float* __restrict__ bk,
                       const float* __restrict__ bv)
{
    int t = threadIdx.x;
    g_bqkv[t] = bq[t]; g_bqkv[256 + t] = bk[t]; g_bqkv[512 + t] = bv[t];
}

// ============================================================================
// Weight transpose + tf32 rounding: Wt[n][k] = round(W[k][n])
// ============================================================================
__global__ void k_tr(const float* __restrict__ W, float* __restrict__ Wt, int K, int N)
{
    __shared__ float t[32][33];
    int n0 = blockIdx.x * 32, k0 = blockIdx.y * 32;
    int x = threadIdx.x, y = threadIdx.y;
    for (int i = y; i < 32; i += 8) t[i][x] = W[(size_t)(k0 + i) * N + n0 + x];
    __syncthreads();
    for (int i = y; i < 32; i += 8)
        Wt[(size_t)(n0 + i) * K + k0 + x] = rtf(t[x][i]);
}

// ============================================================================
// tf32 mma.sync GEMM: Out[m0..+128, n0..+128] = A[128,K] @ Bt[N,K]^T + bias
// A and Bt must already be tf32-rounded (raw bits fed to mma).
// ACT: 0 none | 2 relu + tf32-round | 3 phi if n0<512 else none (QKV merged)
// smem rows padded to 40 floats -> conflict-free LDS.64 fragment loads.
// ============================================================================
__device__ __forceinline__ void stage(const float* __restrict__ Ap,
                                      const float* __restrict__ Bp,
                                      int K, uint32_t sa, uint32_t sb, int tid)
{
#pragma unroll
    for (int t = 0; t < 4; t++) {
        int i = tid + t * 256;
        int row = i >> 3, c4 = i & 7;
        cp16(sa + row * 160 + c4 * 16, Ap + (size_t)row * K + c4 * 4);
    }
#pragma unroll
    for (int t = 0; t < 4; t++) {
        int i = tid + t * 256;
        int row = i >> 3, c4 = i & 7;
        cp16(sb + row * 160 + c4 * 16, Bp + (size_t)row * K + c4 * 4);
    }
}

template <int ACT>
__global__ __launch_bounds__(256, 2) void k_gemm(
    const float* __restrict__ A, const float* __restrict__ Bt,
    const float* __restrict__ bias, float* __restrict__ Out,
    int K, int Nout)
{
    extern __shared__ float sm[];
    float* sAb[2] = { sm,         sm + 5120 };
    float* sBb[2] = { sm + 10240, sm + 15360 };

    const int tid  = threadIdx.x;
    const int wid  = tid >> 5;
    const int lane = tid & 31;
    const int g = lane >> 2, t = lane & 3;
    const int wm = wid & 3, wn = wid >> 2;
    const int m0 = blockIdx.y * 128;
    const int n0 = blockIdx.x * 128;
    const int NC = K >> 5;

    uint32_t uA[2], uB[2];
    uA[0] = smem_u32(sAb[0]); uA[1] = smem_u32(sAb[1]);
    uB[0] = smem_u32(sBb[0]); uB[1] = smem_u32(sBb[1]);

    float c[2][8][4] = {};

    stage(A + (size_t)m0 * K, Bt + (size_t)n0 * K, K, uA[0], uB[0], tid);
    asm volatile("cp.async.commit_group;");

    for (int cc = 0; cc < NC; cc++) {
        const int cur = cc & 1;
        if (cc + 1 < NC) {
            stage(A + (size_t)m0 * K + (cc + 1) * 32,
                  Bt + (size_t)n0 * K + (cc + 1) * 32, K,
                  uA[cur ^ 1], uB[cur ^ 1], tid);
            asm volatile("cp.async.commit_group;");
            asm volatile("cp.async.wait_group 1;");
        } else {
            asm volatile("cp.async.wait_group 0;");
        }
        __syncthreads();

        const float* a_s = sAb[cur];
        const float* b_s = sBb[cur];
#pragma unroll
        for (int s = 0; s < 4; s++) {
            // k-slot relabel: slot t <- logical k=s*8+2t, slot t+4 <- s*8+2t+1
            float2 af[2][2];
#pragma unroll
            for (int i = 0; i < 2; i++) {
                const int rb = (2 * wm + i) * 16;
                af[i][0] = *(const float2*)&a_s[(rb + g)     * 40 + s * 8 + 2 * t];
                af[i][1] = *(const float2*)&a_s[(rb + g + 8) * 40 + s * 8 + 2 * t];
            }
            float2 bf[8];
#pragma unroll
            for (int j = 0; j < 8; j++) {
                const int n = (wn * 8 + j) * 8 + g;
                bf[j] = *(const float2*)&b_s[n * 40 + s * 8 + 2 * t];
            }
#pragma unroll
            for (int i = 0; i < 2; i++)
#pragma unroll
                for (int j = 0; j < 8; j++)
                    mma8(c[i][j], af[i][0], af[i][1], bf[j]);
        }
        __syncthreads();
    }

    const bool do_phi = (ACT == 3) && (n0 < 512);
#pragma unroll
    for (int j = 0; j < 8; j++) {
        const int col = n0 + (wn * 8 + j) * 8 + t * 2;
        const float b0 = __ldg(&bias[col]);
        const float b1 = __ldg(&bias[col + 1]);
#pragma unroll
        for (int i = 0; i < 2; i++) {
            const int r0 = m0 + (2 * wm + i) * 16 + g;
            float v0 = c[i][j][0] + b0, v1 = c[i][j][1] + b1;
            float v2 = c[i][j][2] + b0, v3 = c[i][j][3] + b1;
            if (do_phi) {
                v0 = (v0 > 0.f) ? (v0 + 1.f) : expf(v0);
                v1 = (v1 > 0.f) ? (v1 + 1.f) : expf(v1);
                v2 = (v2 > 0.f) ? (v2 + 1.f) : expf(v2);
                v3 = (v3 > 0.f) ? (v3 + 1.f) : expf(v3);
            }
            if (ACT == 2) {
                v0 = rtf(fmaxf(v0, 0.f)); v1 = rtf(fmaxf(v1, 0.f));
                v2 = rtf(fmaxf(v2, 0.f)); v3 = rtf(fmaxf(v3, 0.f));
            }
            *(float2*)&Out[(size_t)r0 * Nout + col]       = make_float2(v0, v1);
            *(float2*)&Out[(size_t)(r0 + 8) * Nout + col] = make_float2(v2, v3);
        }
    }
}

// ============================================================================
// kv reduction (reads k,v slices of g_qkv)
// ============================================================================
__global__ __launch_bounds__(256) void k_kvred()
{
    __shared__ float s_part[8 * 1024];
    __shared__ float s_ksp[8 * 32];
    const int bh = blockIdx.x;
    const int b = bh >> 3, h = bh & 7;
    const int ch = blockIdx.y;
    const int w = threadIdx.x >> 5, lane = threadIdx.x & 31;

    float acc[32];
#pragma unroll
    for (int d = 0; d < 32; d++) acc[d] = 0.f;
    float ks = 0.f;
    const int t0 = ch * CHTOK;
    for (int i = w; i < CHTOK; i += 8) {
        size_t tok = (size_t)b * L_ + t0 + i;
        float kval = g_qkv[tok * 768 + 256 + h * DH_ + lane];
        float vval = g_qkv[tok * 768 + 512 + h * DH_ + lane];
        ks += kval;
#pragma unroll
        for (int d = 0; d < 32; d++) {
            float kd = __shfl_sync(0xffffffffu, kval, d);
            acc[d] += kd * vval;
        }
    }
#pragma unroll
    for (int d = 0; d < 32; d++) s_part[w * 1024 + d * 32 + lane] = acc[d];
    s_ksp[w * 32 + lane] = ks;
    __syncthreads();
    for (int j = threadIdx.x; j < 1024; j += 256) {
        float s = 0.f;
#pragma unroll
        for (int ww = 0; ww < 8; ww++) s += s_part[ww * 1024 + j];
        g_kvpart[((size_t)ch * 32 + bh) * 1024 + j] = s;
    }
    if (threadIdx.x < 32) {
        float s = 0.f;
#pragma unroll
        for (int ww = 0; ww < 8; ww++) s += s_ksp[ww * 32 + threadIdx.x];
        g_kspart[(ch * 32 + bh) * 32 + threadIdx.x] = s;
    }
}

__global__ __launch_bounds__(256) void k_kvfin()
{
    const int bh = blockIdx.x;
    for (int j = threadIdx.x; j < 1024; j += 256) {
        float s = 0.f;
#pragma unroll
        for (int c = 0; c < NCH; c++) s += g_kvpart[((size_t)c * 32 + bh) * 1024 + j];
        g_kv[bh * 1024 + j] = s;
    }
    if (threadIdx.x < 32) {
        float s = 0.f;
#pragma unroll
        for (int c = 0; c < NCH; c++) s += g_kspart[(c * 32 + bh) * 32 + threadIdx.x];
        g_ksum[bh * 32 + threadIdx.x] = s;
    }
}

// ============================================================================
// attention readout (q slice of g_qkv); output tf32-rounded
// ============================================================================
__global__ __launch_bounds__(256) void k_attnread(float* __restrict__ outa)
{
    extern __shared__ float smr[];
    float* s_kv = smr;
    float* s_ks = smr + 8192;
    float* s_z  = smr + 8448;
    float* s_q  = smr + 8704;

    const int tid  = threadIdx.x;
    const int tok0 = blockIdx.x * 32;
    const int b    = tok0 >> 14;

    for (int i = tid; i < 2048; i += 256)
        *(float4*)&s_kv[i * 4] = *(const float4*)&g_kv[b * 8192 + i * 4];
    if (tid < 64)
        *(float4*)&s_ks[tid * 4] = *(const float4*)&g_ksum[b * 256 + tid * 4];
    for (int i = tid; i < 2048; i += 256) {
        int row = i >> 6, c4 = i & 63;
        *(float4*)&s_q[row * 256 + c4 * 4] =
            *(const float4*)&g_qkv[(size_t)(tok0 + row) * 768 + c4 * 4];
    }
    __syncthreads();

    {
        int r = tid & 31, h = tid >> 5;
        float s = 0.f;
#pragma unroll
        for (int d4 = 0; d4 < 8; d4++) {
            float4 q4 = *(float4*)&s_q[r * 256 + h * 32 + d4 * 4];
            float4 k4 = *(float4*)&s_ks[h * 32 + d4 * 4];
            s += q4.x * k4.x + q4.y * k4.y + q4.z * k4.z + q4.w * k4.w;
        }
        s_z[r * 8 + h] = 1.f / (s + 1e-6f);
    }
    __syncthreads();

    {
        int h = tid >> 5, e = tid & 31;
        float kvc[32];
#pragma unroll
        for (int d = 0; d < 32; d++) kvc[d] = s_kv[(h * 32 + d) * 32 + e];
        for (int r = 0; r < 32; r++) {
            float acc = 0.f;
#pragma unroll
            for (int d4 = 0; d4 < 8; d4++) {
                float4 q4 = *(float4*)&s_q[r * 256 + h * 32 + d4 * 4];
                acc += q4.x * kvc[d4 * 4] + q4.y * kvc[d4 * 4 + 1]
                     + q4.z * kvc[d4 * 4 + 2] + q4.w * kvc[d4 * 4 + 3];
            }
            outa[(size_t)(tok0 + r) * D_ + tid] = rtf(acc * s_z[r * 8 + h]);
        }
    }
}

// ============================================================================
// residual + LayerNorm.  Optionally also writes tf32-rounded copy.
// ============================================================================
template <bool WR>
__global__ __launch_bounds__(256) void k_resln(
    const float* __restrict__ ain, const float* __restrict__ bin,
    const float* __restrict__ g, const float* __restrict__ be,
    float* __restrict__ o, float* __restrict__ orr)
{
    const int tid = threadIdx.x;
    const int tok0 = blockIdx.x * 32;
    const int w = tid >> 5, lane = tid & 31;
#pragma unroll
    for (int rr = 0; rr < 4; rr++) {
        int row = w * 4 + rr;
        size_t rb = (size_t)(tok0 + row) * D_;
        float vals[8];
        float sum = 0.f, sq = 0.f;
#pragma unroll
        for (int i = 0; i < 8; i++) {
            float v = ain[rb + lane + i * 32] + bin[rb + lane + i * 32];
            vals[i] = v; sum += v; sq += v * v;
        }
#pragma unroll
        for (int off = 16; off > 0; off >>= 1) {
            sum += __shfl_xor_sync(0xffffffffu, sum, off);
            sq  += __shfl_xor_sync(0xffffffffu, sq,  off);
        }
        float mu  = sum * (1.f / 256.f);
        float var = sq * (1.f / 256.f) - mu * mu;
        float rs  = rsqrtf(var + 1e-5f);
#pragma unroll
        for (int i = 0; i < 8; i++) {
            int col = lane + i * 32;
            float v = (vals[i] - mu) * rs * g[col] + be[col];
            o[rb + col] = v;
            if (WR) orr[rb + col] = rtf(v);
        }
    }
}

// ============================================================================
extern "C" void kernel_launch(void* const* d_in, const int* in_sizes, int n_in,
                              void* d_out, int out_size)
{
    const float* x    = (const float*)d_in[0];
    const float* Wq   = (const float*)d_in[1];
    const float* bq   = (const float*)d_in[2];
    const float* Wk   = (const float*)d_in[3];
    const float* bk   = (const float*)d_in[4];
    const float* Wv   = (const float*)d_in[5];
    const float* bv   = (const float*)d_in[6];
    const float* Wo   = (const float*)d_in[7];
    const float* bo   = (const float*)d_in[8];
    const float* W1   = (const float*)d_in[9];
    const float* b1   = (const float*)d_in[10];
    const float* W2   = (const float*)d_in[11];
    const float* b2   = (const float*)d_in[12];
    const float* ln1g = (const float*)d_in[13];
    const float* ln1b = (const float*)d_in[14];
    const float* ln2g = (const float*)d_in[15];
    const float* ln2b = (const float*)d_in[16];
    float* out = (float*)d_out;

    float *xr, *qkv, *a, *y, *x1, *x1r, *h;
    float *wqkvT, *woT, *w1T, *w2T, *bqkv;
    cudaGetSymbolAddress((void**)&xr,    g_xr);
    cudaGetSymbolAddress((void**)&qkv,   g_qkv);
    cudaGetSymbolAddress((void**)&a,     g_a);
    cudaGetSymbolAddress((void**)&y,     g_y);
    cudaGetSymbolAddress((void**)&x1,    g_x1);
    cudaGetSymbolAddress((void**)&x1r,   g_x1r);
    cudaGetSymbolAddress((void**)&h,     g_h);
    cudaGetSymbolAddress((void**)&wqkvT, g_wqkvT);
    cudaGetSymbolAddress((void**)&woT,   g_woT);
    cudaGetSymbolAddress((void**)&w1T,   g_w1T);
    cudaGetSymbolAddress((void**)&w2T,   g_w2T);
    cudaGetSymbolAddress((void**)&bqkv,  g_bqkv);

    const int GSM = 81920;
    cudaFuncSetAttribute(k_gemm<0>, cudaFuncAttributeMaxDynamicSharedMemorySize, GSM);
    cudaFuncSetAttribute(k_gemm<2>, cudaFuncAttributeMaxDynamicSharedMemorySize, GSM);
    cudaFuncSetAttribute(k_gemm<3>, cudaFuncAttributeMaxDynamicSharedMemorySize, GSM);
    cudaFuncSetAttribute(k_attnread, cudaFuncAttributeMaxDynamicSharedMemorySize, 67584);

    k_roundx<<<MTOK * D_ / 4 / 512, 512>>>(x);
    k_catb<<<1, 256>>>(bq, bk, bv);

    dim3 trb(32, 8);
    k_tr<<<dim3(8, 8),  trb>>>(Wq, wqkvT,             D_, D_);
    k_tr<<<dim3(8, 8),  trb>>>(Wk, wqkvT + 256 * D_,  D_, D_);
    k_tr<<<dim3(8, 8),  trb>>>(Wv, wqkvT + 512 * D_,  D_, D_);
    k_tr<<<dim3(8, 8),  trb>>>(Wo, woT, D_, D_);
    k_tr<<<dim3(32, 8), trb>>>(W1, w1T, D_, FF_);
    k_tr<<<dim3(8, 32), trb>>>(W2, w2T, FF_, D_);

    // merged QKV projection (phi fused for q,k cols)
    k_gemm<3><<<dim3(6, 512), 256, GSM>>>(xr, wqkvT, bqkv, qkv, D_, 768);

    k_kvred<<<dim3(32, NCH), 256>>>();
    k_kvfin<<<32, 256>>>();
    k_attnread<<<MTOK / 32, 256, 67584>>>(a);

    // Wo projection + residual/LN1
    k_gemm<0><<<dim3(2, 512), 256, GSM>>>(a, woT, bo, y, D_, D_);
    k_resln<true><<<MTOK / 32, 256>>>(x, y, ln1g, ln1b, x1, x1r);

    // FFN
    k_gemm<2><<<dim3(8, 512), 256, GSM>>>(x1r, w1T, b1, h, D_, FF_);
    k_gemm<0><<<dim3(2, 512), 256, GSM>>>(h, w2T, b2, y, FF_, D_);
    k_resln<false><<<MTOK / 32, 256>>>(x1, y, ln2g, ln2b, out, out);
}

// round 5
// speedup vs baseline: 4.7006x; 1.3537x over previous
#include <cuda_runtime.h>
#include <cuda_fp16.h>
#include <math.h>
#include <stdint.h>

#define B_    4
#define L_    16384
#define D_    256
#define H_    8
#define DH_   32
#define FF_   1024
#define MTOK  65536
#define NCH   16
#define CHTOK 1024

// ---------------- scratch ----------------
__device__ __half g_xh [MTOK * D_];      // x as half
__device__ float  g_qkv[MTOK * 768];     // q|k|v per token (f32)
__device__ __half g_ah [MTOK * D_];      // attn readout (half)
__device__ float  g_y  [MTOK * D_];
__device__ float  g_x1 [MTOK * D_];
__device__ __half g_x1h[MTOK * D_];
__device__ __half g_hh [MTOK * FF_];     // ffn hidden (half)
__device__ float  g_kvpart[NCH * 32 * 1024];
__device__ float  g_kspart[NCH * 32 * 32];
__device__ float  g_kv[32 * 1024];
__device__ float  g_ksum[32 * 32];
// transposed weights [N,K] row-major, half
__device__ __half g_wqkvT[768 * D_];
__device__ __half g_woT[D_ * D_];
__device__ __half g_w1T[FF_ * D_];
__device__ __half g_w2T[D_ * FF_];
__device__ float  g_bqkv[768];

// ---------------- helpers ----------------
__device__ __forceinline__ uint32_t smem_u32(const void* p) {
    uint32_t a;
    asm("{ .reg .u64 t; cvta.to.shared.u64 t, %1; cvt.u32.u64 %0, t; }" : "=r"(a) : "l"(p));
    return a;
}
__device__ __forceinline__ void cp16(uint32_t dst, const void* src) {
    asm volatile("cp.async.cg.shared.global [%0], [%1], 16;" :: "r"(dst), "l"(src));
}
__device__ __forceinline__ void mma16(float* c, uint32_t a0, uint32_t a1,
                                      uint32_t a2, uint32_t a3,
                                      uint32_t b0, uint32_t b1) {
    asm volatile("mma.sync.aligned.m16n8k16.row.col.f32.f16.f16.f32 "
        "{%0,%1,%2,%3}, {%4,%5,%6,%7}, {%8,%9}, {%0,%1,%2,%3};"
        : "+f"(c[0]), "+f"(c[1]), "+f"(c[2]), "+f"(c[3])
        : "r"(a0), "r"(a1), "r"(a2), "r"(a3), "r"(b0), "r"(b1));
}

// ============================================================================
// x -> half copy
// ============================================================================
__global__ __launch_bounds__(512) void k_cvtx(const float* __restrict__ x)
{
    int i = blockIdx.x * 512 + threadIdx.x;       // one float4 each
    float4 v = *(const float4*)&x[(size_t)i * 4];
    __half2 h0 = __floats2half2_rn(v.x, v.y);
    __half2 h1 = __floats2half2_rn(v.z, v.w);
    *(uint2*)&g_xh[(size_t)i * 4] = make_uint2(
        *(uint32_t*)&h0, *(uint32_t*)&h1);
}

__global__ void k_catb(const float* __restrict__ bq, const float* __restrict__ bk,
                       const float* __restrict__ bv)
{
    int t = threadIdx.x;
    g_bqkv[t] = bq[t]; g_bqkv[256 + t] = bk[t]; g_bqkv[512 + t] = bv[t];
}

// ============================================================================
// Weight transpose + half: Wt[n][k] = half(W[k][n])
// ============================================================================
__global__ void k_tr(const float* __restrict__ W, __half* __restrict__ Wt, int K, int N)
{
    __shared__ float t[32][33];
    int n0 = blockIdx.x * 32, k0 = blockIdx.y * 32;
    int x = threadIdx.x, y = threadIdx.y;
    for (int i = y; i < 32; i += 8) t[i][x] = W[(size_t)(k0 + i) * N + n0 + x];
    __syncthreads();
    for (int i = y; i < 32; i += 8)
        Wt[(size_t)(n0 + i) * K + k0 + x] = __float2half(t[x][i]);
}

// ============================================================================
// fp16 mma.sync GEMM: Out[m0..+128, n0..+128] = A[128,K] @ Bt[N,K]^T + bias
// ACT: 0 none | 2 relu | 3 phi if n0<512 (merged QKV)
// OUTH: 1 -> half output, 0 -> f32.
// smem rows: 32 halves padded to 48 (96B) -> conflict-free LDS.64 frag loads.
// ============================================================================
__device__ __forceinline__ void stage(const __half* __restrict__ Ap,
                                      const __half* __restrict__ Bp,
                                      int K, uint32_t sa, uint32_t sb, int tid)
{
#pragma unroll
    for (int t = 0; t < 2; t++) {
        int i = tid + t * 256;
        int row = i >> 2, c = i & 3;
        cp16(sa + row * 96 + c * 16, Ap + (size_t)row * K + c * 8);
    }
#pragma unroll
    for (int t = 0; t < 2; t++) {
        int i = tid + t * 256;
        int row = i >> 2, c = i & 3;
        cp16(sb + row * 96 + c * 16, Bp + (size_t)row * K + c * 8);
    }
}

template <int ACT, int OUTH>
__global__ __launch_bounds__(256, 2) void k_gemm(
    const __half* __restrict__ A, const __half* __restrict__ Bt,
    const float* __restrict__ bias, void* __restrict__ OutV,
    int K, int Nout)
{
    extern __shared__ __half smh[];
    __half* sAb[2] = { smh,         smh + 6144 };
    __half* sBb[2] = { smh + 12288, smh + 18432 };

    const int tid  = threadIdx.x;
    const int wid  = tid >> 5;
    const int lane = tid & 31;
    const int g = lane >> 2, t = lane & 3;
    const int wm = wid & 3, wn = wid >> 2;
    const int m0 = blockIdx.y * 128;
    const int n0 = blockIdx.x * 128;
    const int NC = K >> 5;

    uint32_t uA[2], uB[2];
    uA[0] = smem_u32(sAb[0]); uA[1] = smem_u32(sAb[1]);
    uB[0] = smem_u32(sBb[0]); uB[1] = smem_u32(sBb[1]);

    float c[2][8][4] = {};

    stage(A + (size_t)m0 * K, Bt + (size_t)n0 * K, K, uA[0], uB[0], tid);
    asm volatile("cp.async.commit_group;");

    for (int cc = 0; cc < NC; cc++) {
        const int cur = cc & 1;
        if (cc + 1 < NC) {
            stage(A + (size_t)m0 * K + (cc + 1) * 32,
                  Bt + (size_t)n0 * K + (cc + 1) * 32, K,
                  uA[cur ^ 1], uB[cur ^ 1], tid);
            asm volatile("cp.async.commit_group;");
            asm volatile("cp.async.wait_group 1;");
        } else {
            asm volatile("cp.async.wait_group 0;");
        }
        __syncthreads();

        const __half* a_s = sAb[cur];
        const __half* b_s = sBb[cur];
#pragma unroll
        for (int s = 0; s < 2; s++) {
            // virtual k relabel: mma k-slots {2t,2t+1,2t+8,2t+9} <- logical 4t..4t+3
            uint2 va[2][2];
#pragma unroll
            for (int i = 0; i < 2; i++) {
                const int rb = (2 * wm + i) * 16;
                va[i][0] = *(const uint2*)&a_s[(rb + g)     * 48 + s * 16 + 4 * t];
                va[i][1] = *(const uint2*)&a_s[(rb + g + 8) * 48 + s * 16 + 4 * t];
            }
            uint2 vb[8];
#pragma unroll
            for (int j = 0; j < 8; j++) {
                const int n = (wn * 8 + j) * 8 + g;
                vb[j] = *(const uint2*)&b_s[n * 48 + s * 16 + 4 * t];
            }
#pragma unroll
            for (int i = 0; i < 2; i++)
#pragma unroll
                for (int j = 0; j < 8; j++)
                    mma16(c[i][j], va[i][0].x, va[i][1].x, va[i][0].y, va[i][1].y,
                          vb[j].x, vb[j].y);
        }
        __syncthreads();
    }

    const bool do_phi = (ACT == 3) && (n0 < 512);
#pragma unroll
    for (int j = 0; j < 8; j++) {
        const int col = n0 + (wn * 8 + j) * 8 + t * 2;
        const float b0 = __ldg(&bias[col]);
        const float b1 = __ldg(&bias[col + 1]);
#pragma unroll
        for (int i = 0; i < 2; i++) {
            const int r0 = m0 + (2 * wm + i) * 16 + g;
            float v0 = c[i][j][0] + b0, v1 = c[i][j][1] + b1;
            float v2 = c[i][j][2] + b0, v3 = c[i][j][3] + b1;
            if (do_phi) {
                v0 = (v0 > 0.f) ? (v0 + 1.f) : expf(v0);
                v1 = (v1 > 0.f) ? (v1 + 1.f) : expf(v1);
                v2 = (v2 > 0.f) ? (v2 + 1.f) : expf(v2);
                v3 = (v3 > 0.f) ? (v3 + 1.f) : expf(v3);
            }
            if (ACT == 2) {
                v0 = fmaxf(v0, 0.f); v1 = fmaxf(v1, 0.f);
                v2 = fmaxf(v2, 0.f); v3 = fmaxf(v3, 0.f);
            }
            if (OUTH) {
                __half* Out = (__half*)OutV;
                __half2 h0 = __floats2half2_rn(v0, v1);
                __half2 h1 = __floats2half2_rn(v2, v3);
                *(__half2*)&Out[(size_t)r0 * Nout + col]       = h0;
                *(__half2*)&Out[(size_t)(r0 + 8) * Nout + col] = h1;
            } else {
                float* Out = (float*)OutV;
                *(float2*)&Out[(size_t)r0 * Nout + col]       = make_float2(v0, v1);
                *(float2*)&Out[(size_t)(r0 + 8) * Nout + col] = make_float2(v2, v3);
            }
        }
    }
}

// ============================================================================
// kv reduction (reads k,v slices of g_qkv, f32)
// ============================================================================
__global__ __launch_bounds__(256) void k_kvred()
{
    __shared__ float s_part[8 * 1024];
    __shared__ float s_ksp[8 * 32];
    const int bh = blockIdx.x;
    const int b = bh >> 3, h = bh & 7;
    const int ch = blockIdx.y;
    const int w = threadIdx.x >> 5, lane = threadIdx.x & 31;

    float acc[32];
#pragma unroll
    for (int d = 0; d < 32; d++) acc[d] = 0.f;
    float ks = 0.f;
    const int t0 = ch * CHTOK;
    for (int i = w; i < CHTOK; i += 8) {
        size_t tok = (size_t)b * L_ + t0 + i;
        float kval = g_qkv[tok * 768 + 256 + h * DH_ + lane];
        float vval = g_qkv[tok * 768 + 512 + h * DH_ + lane];
        ks += kval;
#pragma unroll
        for (int d = 0; d < 32; d++) {
            float kd = __shfl_sync(0xffffffffu, kval, d);
            acc[d] += kd * vval;
        }
    }
#pragma unroll
    for (int d = 0; d < 32; d++) s_part[w * 1024 + d * 32 + lane] = acc[d];
    s_ksp[w * 32 + lane] = ks;
    __syncthreads();
    for (int j = threadIdx.x; j < 1024; j += 256) {
        float s = 0.f;
#pragma unroll
        for (int ww = 0; ww < 8; ww++) s += s_part[ww * 1024 + j];
        g_kvpart[((size_t)ch * 32 + bh) * 1024 + j] = s;
    }
    if (threadIdx.x < 32) {
        float s = 0.f;
#pragma unroll
        for (int ww = 0; ww < 8; ww++) s += s_ksp[ww * 32 + threadIdx.x];
        g_kspart[(ch * 32 + bh) * 32 + threadIdx.x] = s;
    }
}

__global__ __launch_bounds__(256) void k_kvfin()
{
    const int bh = blockIdx.x;
    for (int j = threadIdx.x; j < 1024; j += 256) {
        float s = 0.f;
#pragma unroll
        for (int c = 0; c < NCH; c++) s += g_kvpart[((size_t)c * 32 + bh) * 1024 + j];
        g_kv[bh * 1024 + j] = s;
    }
    if (threadIdx.x < 32) {
        float s = 0.f;
#pragma unroll
        for (int c = 0; c < NCH; c++) s += g_kspart[(c * 32 + bh) * 32 + threadIdx.x];
        g_ksum[bh * 32 + threadIdx.x] = s;
    }
}

// ============================================================================
// attention readout (q slice of g_qkv); output half
// ============================================================================
__global__ __launch_bounds__(256) void k_attnread(__half* __restrict__ outa)
{
    extern __shared__ float smr[];
    float* s_kv = smr;
    float* s_ks = smr + 8192;
    float* s_z  = smr + 8448;
    float* s_q  = smr + 8704;

    const int tid  = threadIdx.x;
    const int tok0 = blockIdx.x * 32;
    const int b    = tok0 >> 14;

    for (int i = tid; i < 2048; i += 256)
        *(float4*)&s_kv[i * 4] = *(const float4*)&g_kv[b * 8192 + i * 4];
    if (tid < 64)
        *(float4*)&s_ks[tid * 4] = *(const float4*)&g_ksum[b * 256 + tid * 4];
    for (int i = tid; i < 2048; i += 256) {
        int row = i >> 6, c4 = i & 63;
        *(float4*)&s_q[row * 256 + c4 * 4] =
            *(const float4*)&g_qkv[(size_t)(tok0 + row) * 768 + c4 * 4];
    }
    __syncthreads();

    {
        int r = tid & 31, h = tid >> 5;
        float s = 0.f;
#pragma unroll
        for (int d4 = 0; d4 < 8; d4++) {
            float4 q4 = *(float4*)&s_q[r * 256 + h * 32 + d4 * 4];
            float4 k4 = *(float4*)&s_ks[h * 32 + d4 * 4];
            s += q4.x * k4.x + q4.y * k4.y + q4.z * k4.z + q4.w * k4.w;
        }
        s_z[r * 8 + h] = 1.f / (s + 1e-6f);
    }
    __syncthreads();

    {
        int h = tid >> 5, e = tid & 31;
        float kvc[32];
#pragma unroll
        for (int d = 0; d < 32; d++) kvc[d] = s_kv[(h * 32 + d) * 32 + e];
        for (int r = 0; r < 32; r++) {
            float acc = 0.f;
#pragma unroll
            for (int d4 = 0; d4 < 8; d4++) {
                float4 q4 = *(float4*)&s_q[r * 256 + h * 32 + d4 * 4];
                acc += q4.x * kvc[d4 * 4] + q4.y * kvc[d4 * 4 + 1]
                     + q4.z * kvc[d4 * 4 + 2] + q4.w * kvc[d4 * 4 + 3];
            }
            outa[(size_t)(tok0 + r) * D_ + tid] = __float2half(acc * s_z[r * 8 + h]);
        }
    }
}

// ============================================================================
// residual + LayerNorm.  Optionally also writes half copy.
// ============================================================================
template <bool WH>
__global__ __launch_bounds__(256) void k_resln(
    const float* __restrict__ ain, const float* __restrict__ bin,
    const float* __restrict__ g, const float* __restrict__ be,
    float* __restrict__ o, __half* __restrict__ oh)
{
    const int tid = threadIdx.x;
    const int tok0 = blockIdx.x * 32;
    const int w = tid >> 5, lane = tid & 31;
#pragma unroll
    for (int rr = 0; rr < 4; rr++) {
        int row = w * 4 + rr;
        size_t rb = (size_t)(tok0 + row) * D_;
        float vals[8];
        float sum = 0.f, sq = 0.f;
#pragma unroll
        for (int i = 0; i < 8; i++) {
            float v = ain[rb + lane + i * 32] + bin[rb + lane + i * 32];
            vals[i] = v; sum += v; sq += v * v;
        }
#pragma unroll
        for (int off = 16; off > 0; off >>= 1) {
            sum += __shfl_xor_sync(0xffffffffu, sum, off);
            sq  += __shfl_xor_sync(0xffffffffu, sq,  off);
        }
        float mu  = sum * (1.f / 256.f);
        float var = sq * (1.f / 256.f) - mu * mu;
        float rs  = rsqrtf(var + 1e-5f);
#pragma unroll
        for (int i = 0; i < 8; i++) {
            int col = lane + i * 32;
            float v = (vals[i] - mu) * rs * g[col] + be[col];
            o[rb + col] = v;
            if (WH) oh[rb + col] = __float2half(v);
        }
    }
}

// ============================================================================
extern "C" void kernel_launch(void* const* d_in, const int* in_sizes, int n_in,
                              void* d_out, int out_size)
{
    const float* x    = (const float*)d_in[0];
    const float* Wq   = (const float*)d_in[1];
    const float* bq   = (const float*)d_in[2];
    const float* Wk   = (const float*)d_in[3];
    const float* bk   = (const float*)d_in[4];
    const float* Wv   = (const float*)d_in[5];
    const float* bv   = (const float*)d_in[6];
    const float* Wo   = (const float*)d_in[7];
    const float* bo   = (const float*)d_in[8];
    const float* W1   = (const float*)d_in[9];
    const float* b1   = (const float*)d_in[10];
    const float* W2   = (const float*)d_in[11];
    const float* b2   = (const float*)d_in[12];
    const float* ln1g = (const float*)d_in[13];
    const float* ln1b = (const float*)d_in[14];
    const float* ln2g = (const float*)d_in[15];
    const float* ln2b = (const float*)d_in[16];
    float* out = (float*)d_out;

    __half *xh, *ah, *x1h, *hh, *wqkvT, *woT, *w1T, *w2T;
    float *qkv, *y, *x1, *bqkv;
    cudaGetSymbolAddress((void**)&xh,    g_xh);
    cudaGetSymbolAddress((void**)&qkv,   g_qkv);
    cudaGetSymbolAddress((void**)&ah,    g_ah);
    cudaGetSymbolAddress((void**)&y,     g_y);
    cudaGetSymbolAddress((void**)&x1,    g_x1);
    cudaGetSymbolAddress((void**)&x1h,   g_x1h);
    cudaGetSymbolAddress((void**)&hh,    g_hh);
    cudaGetSymbolAddress((void**)&wqkvT, g_wqkvT);
    cudaGetSymbolAddress((void**)&woT,   g_woT);
    cudaGetSymbolAddress((void**)&w1T,   g_w1T);
    cudaGetSymbolAddress((void**)&w2T,   g_w2T);
    cudaGetSymbolAddress((void**)&bqkv,  g_bqkv);

    const int GSM = 49152;
    cudaFuncSetAttribute((k_gemm<0,0>), cudaFuncAttributeMaxDynamicSharedMemorySize, GSM);
    cudaFuncSetAttribute((k_gemm<2,1>), cudaFuncAttributeMaxDynamicSharedMemorySize, GSM);
    cudaFuncSetAttribute((k_gemm<3,0>), cudaFuncAttributeMaxDynamicSharedMemorySize, GSM);
    cudaFuncSetAttribute(k_attnread, cudaFuncAttributeMaxDynamicSharedMemorySize, 67584);

    k_cvtx<<<MTOK * D_ / 4 / 512, 512>>>(x);
    k_catb<<<1, 256>>>(bq, bk, bv);

    dim3 trb(32, 8);
    k_tr<<<dim3(8, 8),  trb>>>(Wq, wqkvT,             D_, D_);
    k_tr<<<dim3(8, 8),  trb>>>(Wk, wqkvT + 256 * D_,  D_, D_);
    k_tr<<<dim3(8, 8),  trb>>>(Wv, wqkvT + 512 * D_,  D_, D_);
    k_tr<<<dim3(8, 8),  trb>>>(Wo, woT, D_, D_);
    k_tr<<<dim3(32, 8), trb>>>(W1, w1T, D_, FF_);
    k_tr<<<dim3(8, 32), trb>>>(W2, w2T, FF_, D_);

    // merged QKV projection (phi fused for q,k cols), f32 out
    k_gemm<3,0><<<dim3(6, 512), 256, GSM>>>(xh, wqkvT, bqkv, qkv, D_, 768);

    k_kvred<<<dim3(32, NCH), 256>>>();
    k_kvfin<<<32, 256>>>();
    k_attnread<<<MTOK / 32, 256, 67584>>>(ah);

    // Wo projection + residual/LN1
    k_gemm<0,0><<<dim3(2, 512), 256, GSM>>>(ah, woT, bo, y, D_, D_);
    k_resln<true><<<MTOK / 32, 256>>>(x, y, ln1g, ln1b, x1, x1h);

    // FFN
    k_gemm<2,1><<<dim3(8, 512), 256, GSM>>>(x1h, w1T, b1, hh, D_, FF_);
    k_gemm<0,0><<<dim3(2, 512), 256, GSM>>>(hh, w2T, b2, y, FF_, D_);
    k_resln<false><<<MTOK / 32, 256>>>(x1, y, ln2g, ln2b, out, nullptr);
}

// round 7
// speedup vs baseline: 4.8231x; 1.0261x over previous
#include <cuda_runtime.h>
#include <cuda_fp16.h>
#include <math.h>
#include <stdint.h>

#define B_    4
#define L_    16384
#define D_    256
#define H_    8
#define DH_   32
#define FF_   1024
#define MTOK  65536
#define NCH   16
#define CHTOK 1024

// ---------------- scratch ----------------
__device__ __half g_xh  [MTOK * D_];     // x as half
__device__ __half g_qkvh[MTOK * 768];    // q|k|v per token (half)
__device__ __half g_ah  [MTOK * D_];     // attn readout (half)
__device__ float  g_y   [MTOK * D_];
__device__ float  g_x1  [MTOK * D_];
__device__ __half g_x1h [MTOK * D_];
__device__ __half g_hh  [MTOK * FF_];    // ffn hidden (half)
__device__ float  g_kvpart[NCH * 32 * 1024];
__device__ float  g_kspart[NCH * 32 * 32];
__device__ float  g_kv[32 * 1024];
__device__ float  g_ksum[32 * 32];
// transposed weights [N,K] row-major, half
__device__ __half g_wqkvT[768 * D_];
__device__ __half g_woT[D_ * D_];
__device__ __half g_w1T[FF_ * D_];
__device__ __half g_w2T[D_ * FF_];
__device__ float  g_bqkv[768];

// ---------------- helpers ----------------
__device__ __forceinline__ uint32_t smem_u32(const void* p) {
    uint32_t a;
    asm("{ .reg .u64 t; cvta.to.shared.u64 t, %1; cvt.u32.u64 %0, t; }" : "=r"(a) : "l"(p));
    return a;
}
__device__ __forceinline__ void cp16(uint32_t dst, const void* src) {
    asm volatile("cp.async.cg.shared.global [%0], [%1], 16;" :: "r"(dst), "l"(src));
}
__device__ __forceinline__ void mma16(float* c, uint32_t a0, uint32_t a1,
                                      uint32_t a2, uint32_t a3,
                                      uint32_t b0, uint32_t b1) {
    asm volatile("mma.sync.aligned.m16n8k16.row.col.f32.f16.f16.f32 "
        "{%0,%1,%2,%3}, {%4,%5,%6,%7}, {%8,%9}, {%0,%1,%2,%3};"
        : "+f"(c[0]), "+f"(c[1]), "+f"(c[2]), "+f"(c[3])
        : "r"(a0), "r"(a1), "r"(a2), "r"(a3), "r"(b0), "r"(b1));
}

// ============================================================================
// x -> half copy
// ============================================================================
__global__ __launch_bounds__(512) void k_cvtx(const float* __restrict__ x)
{
    int i = blockIdx.x * 512 + threadIdx.x;       // one float4 each
    float4 v = *(const float4*)&x[(size_t)i * 4];
    __half2 h0 = __floats2half2_rn(v.x, v.y);
    __half2 h1 = __floats2half2_rn(v.z, v.w);
    *(uint2*)&g_xh[(size_t)i * 4] = make_uint2(
        *(uint32_t*)&h0, *(uint32_t*)&h1);
}

__global__ void k_catb(const float* __restrict__ bq, const float* __restrict__ bk,
                       const float* __restrict__ bv)
{
    int t = threadIdx.x;
    g_bqkv[t] = bq[t]; g_bqkv[256 + t] = bk[t]; g_bqkv[512 + t] = bv[t];
}

// ============================================================================
// Weight transpose + half: Wt[n][k] = half(W[k][n])
// ============================================================================
__global__ void k_tr(const float* __restrict__ W, __half* __restrict__ Wt, int K, int N)
{
    __shared__ float t[32][33];
    int n0 = blockIdx.x * 32, k0 = blockIdx.y * 32;
    int x = threadIdx.x, y = threadIdx.y;
    for (int i = y; i < 32; i += 8) t[i][x] = W[(size_t)(k0 + i) * N + n0 + x];
    __syncthreads();
    for (int i = y; i < 32; i += 8)
        Wt[(size_t)(n0 + i) * K + k0 + x] = __float2half(t[x][i]);
}

// ============================================================================
// fp16 mma.sync GEMM: Out[m0..+128, n0..+128] = A[128,K] @ Bt[N,K]^T + bias
// ACT: 0 none | 2 relu | 3 phi if n0<512 (merged QKV)
// OUTH: 1 -> half output, 0 -> f32.
// 3-stage cp.async pipeline, one __syncthreads per chunk.
// smem rows: 32 halves padded to 48 (96B) -> conflict-free LDS.64 frag loads.
// ============================================================================
__device__ __forceinline__ void stage(const __half* __restrict__ Ap,
                                      const __half* __restrict__ Bp,
                                      int K, uint32_t sa, uint32_t sb, int tid)
{
#pragma unroll
    for (int t = 0; t < 2; t++) {
        int i = tid + t * 256;
        int row = i >> 2, c = i & 3;
        cp16(sa + row * 96 + c * 16, Ap + (size_t)row * K + c * 8);
    }
#pragma unroll
    for (int t = 0; t < 2; t++) {
        int i = tid + t * 256;
        int row = i >> 2, c = i & 3;
        cp16(sb + row * 96 + c * 16, Bp + (size_t)row * K + c * 8);
    }
}

template <int ACT, int OUTH>
__global__ __launch_bounds__(256, 2) void k_gemm(
    const __half* __restrict__ A, const __half* __restrict__ Bt,
    const float* __restrict__ bias, void* __restrict__ OutV,
    int K, int Nout)
{
    extern __shared__ __half smh[];
    const int tid  = threadIdx.x;
    const int wid  = tid >> 5;
    const int lane = tid & 31;
    const int g = lane >> 2, t = lane & 3;
    const int wm = wid & 3, wn = wid >> 2;
    const int m0 = blockIdx.y * 128;
    const int n0 = blockIdx.x * 128;
    const int NC = K >> 5;

    uint32_t uA[3], uB[3];
#pragma unroll
    for (int s = 0; s < 3; s++) {
        uA[s] = smem_u32(smh + s * 6144);
        uB[s] = smem_u32(smh + 18432 + s * 6144);
    }

    float c[2][8][4] = {};

    const __half* Abase = A + (size_t)m0 * K;
    const __half* Bbase = Bt + (size_t)n0 * K;

    stage(Abase, Bbase, K, uA[0], uB[0], tid);
    asm volatile("cp.async.commit_group;");
    stage(Abase + 32, Bbase + 32, K, uA[1], uB[1], tid);
    asm volatile("cp.async.commit_group;");

    for (int cc = 0; cc < NC; cc++) {
        if (cc + 1 < NC) asm volatile("cp.async.wait_group 1;");
        else             asm volatile("cp.async.wait_group 0;");
        __syncthreads();

        if (cc + 2 < NC) {
            const int bs = (cc + 2) % 3;
            stage(Abase + (cc + 2) * 32, Bbase + (cc + 2) * 32, K,
                  uA[bs], uB[bs], tid);
            asm volatile("cp.async.commit_group;");
        }

        const int cur = cc % 3;
        const __half* a_s = smh + cur * 6144;
        const __half* b_s = smh + 18432 + cur * 6144;
#pragma unroll
        for (int s = 0; s < 2; s++) {
            // virtual k relabel: mma k-slots {2t,2t+1,2t+8,2t+9} <- logical 4t..4t+3
            uint2 va[2][2];
#pragma unroll
            for (int i = 0; i < 2; i++) {
                const int rb = (2 * wm + i) * 16;
                va[i][0] = *(const uint2*)&a_s[(rb + g)     * 48 + s * 16 + 4 * t];
                va[i][1] = *(const uint2*)&a_s[(rb + g + 8) * 48 + s * 16 + 4 * t];
            }
            uint2 vb[8];
#pragma unroll
            for (int j = 0; j < 8; j++) {
                const int n = (wn * 8 + j) * 8 + g;
                vb[j] = *(const uint2*)&b_s[n * 48 + s * 16 + 4 * t];
            }
#pragma unroll
            for (int i = 0; i < 2; i++)
#pragma unroll
                for (int j = 0; j < 8; j++)
                    mma16(c[i][j], va[i][0].x, va[i][1].x, va[i][0].y, va[i][1].y,
                          vb[j].x, vb[j].y);
        }
    }

    const bool do_phi = (ACT == 3) && (n0 < 512);
#pragma unroll
    for (int j = 0; j < 8; j++) {
        const int col = n0 + (wn * 8 + j) * 8 + t * 2;
        const float b0 = __ldg(&bias[col]);
        const float b1 = __ldg(&bias[col + 1]);
#pragma unroll
        for (int i = 0; i < 2; i++) {
            const int r0 = m0 + (2 * wm + i) * 16 + g;
            float v0 = c[i][j][0] + b0, v1 = c[i][j][1] + b1;
            float v2 = c[i][j][2] + b0, v3 = c[i][j][3] + b1;
            if (do_phi) {
                v0 = (v0 > 0.f) ? (v0 + 1.f) : expf(v0);
                v1 = (v1 > 0.f) ? (v1 + 1.f) : expf(v1);
                v2 = (v2 > 0.f) ? (v2 + 1.f) : expf(v2);
                v3 = (v3 > 0.f) ? (v3 + 1.f) : expf(v3);
            }
            if (ACT == 2) {
                v0 = fmaxf(v0, 0.f); v1 = fmaxf(v1, 0.f);
                v2 = fmaxf(v2, 0.f); v3 = fmaxf(v3, 0.f);
            }
            if (OUTH) {
                __half* Out = (__half*)OutV;
                __half2 h0 = __floats2half2_rn(v0, v1);
                __half2 h1 = __floats2half2_rn(v2, v3);
                *(__half2*)&Out[(size_t)r0 * Nout + col]       = h0;
                *(__half2*)&Out[(size_t)(r0 + 8) * Nout + col] = h1;
            } else {
                float* Out = (float*)OutV;
                *(float2*)&Out[(size_t)r0 * Nout + col]       = make_float2(v0, v1);
                *(float2*)&Out[(size_t)(r0 + 8) * Nout + col] = make_float2(v2, v3);
            }
        }
    }
}

// ============================================================================
// kv reduction (reads k,v slices of g_qkvh, half)
// ============================================================================
__global__ __launch_bounds__(256) void k_kvred()
{
    __shared__ float s_part[8 * 1024];
    __shared__ float s_ksp[8 * 32];
    const int bh = blockIdx.x;
    const int b = bh >> 3, h = bh & 7;
    const int ch = blockIdx.y;
    const int w = threadIdx.x >> 5, lane = threadIdx.x & 31;

    float acc[32];
#pragma unroll
    for (int d = 0; d < 32; d++) acc[d] = 0.f;
    float ks = 0.f;
    const int t0 = ch * CHTOK;
    for (int i = w; i < CHTOK; i += 8) {
        size_t tok = (size_t)b * L_ + t0 + i;
        float kval = __half2float(g_qkvh[tok * 768 + 256 + h * DH_ + lane]);
        float vval = __half2float(g_qkvh[tok * 768 + 512 + h * DH_ + lane]);
        ks += kval;
#pragma unroll
        for (int d = 0; d < 32; d++) {
            float kd = __shfl_sync(0xffffffffu, kval, d);
            acc[d] += kd * vval;
        }
    }
#pragma unroll
    for (int d = 0; d < 32; d++) s_part[w * 1024 + d * 32 + lane] = acc[d];
    s_ksp[w * 32 + lane] = ks;
    __syncthreads();
    for (int j = threadIdx.x; j < 1024; j += 256) {
        float s = 0.f;
#pragma unroll
        for (int ww = 0; ww < 8; ww++) s += s_part[ww * 1024 + j];
        g_kvpart[((size_t)ch * 32 + bh) * 1024 + j] = s;
    }
    if (threadIdx.x < 32) {
        float s = 0.f;
#pragma unroll
        for (int ww = 0; ww < 8; ww++) s += s_ksp[ww * 32 + threadIdx.x];
        g_kspart[(ch * 32 + bh) * 32 + threadIdx.x] = s;
    }
}

__global__ __launch_bounds__(256) void k_kvfin()
{
    const int bh = blockIdx.x;
    for (int j = threadIdx.x; j < 1024; j += 256) {
        float s = 0.f;
#pragma unroll
        for (int c = 0; c < NCH; c++) s += g_kvpart[((size_t)c * 32 + bh) * 1024 + j];
        g_kv[bh * 1024 + j] = s;
    }
    if (threadIdx.x < 32) {
        float s = 0.f;
#pragma unroll
        for (int c = 0; c < NCH; c++) s += g_kspart[(c * 32 + bh) * 32 + threadIdx.x];
        g_ksum[bh * 32 + threadIdx.x] = s;
    }
}

// ============================================================================
// attention readout (q slice of g_qkvh, half); output half
// ============================================================================
__global__ __launch_bounds__(256) void k_attnread(__half* __restrict__ outa)
{
    extern __shared__ float smr[];
    float* s_kv = smr;          // 8192
    float* s_ks = smr + 8192;   // 256
    float* s_z  = smr + 8448;   // 256
    float* s_q  = smr + 8704;   // 8192

    const int tid  = threadIdx.x;
    const int tok0 = blockIdx.x * 32;
    const int b    = tok0 >> 14;

    for (int i = tid; i < 2048; i += 256)
        *(float4*)&s_kv[i * 4] = *(const float4*)&g_kv[b * 8192 + i * 4];
    if (tid < 64)
        *(float4*)&s_ks[tid * 4] = *(const float4*)&g_ksum[b * 256 + tid * 4];
    // q: 32 tokens x 64 groups of 4 halves = all 256 cols per token
    for (int i = tid; i < 2048; i += 256) {
        int row = i >> 6, c = i & 63;
        uint2 u = *(const uint2*)&g_qkvh[(size_t)(tok0 + row) * 768 + c * 4];
        float2 f0 = __half22float2(*(__half2*)&u.x);
        float2 f1 = __half22float2(*(__half2*)&u.y);
        *(float4*)&s_q[row * 256 + c * 4] = make_float4(f0.x, f0.y, f1.x, f1.y);
    }
    __syncthreads();

    {
        int r = tid & 31, h = tid >> 5;
        float s = 0.f;
#pragma unroll
        for (int d4 = 0; d4 < 8; d4++) {
            float4 q4 = *(float4*)&s_q[r * 256 + h * 32 + d4 * 4];
            float4 k4 = *(float4*)&s_ks[h * 32 + d4 * 4];
            s += q4.x * k4.x + q4.y * k4.y + q4.z * k4.z + q4.w * k4.w;
        }
        s_z[r * 8 + h] = 1.f / (s + 1e-6f);
    }
    __syncthreads();

    {
        int h = tid >> 5, e = tid & 31;
        float kvc[32];
#pragma unroll
        for (int d = 0; d < 32; d++) kvc[d] = s_kv[(h * 32 + d) * 32 + e];
        for (int r = 0; r < 32; r++) {
            float acc = 0.f;
#pragma unroll
            for (int d4 = 0; d4 < 8; d4++) {
                float4 q4 = *(float4*)&s_q[r * 256 + h * 32 + d4 * 4];
                acc += q4.x * kvc[d4 * 4] + q4.y * kvc[d4 * 4 + 1]
                     + q4.z * kvc[d4 * 4 + 2] + q4.w * kvc[d4 * 4 + 3];
            }
            outa[(size_t)(tok0 + r) * D_ + tid] = __float2half(acc * s_z[r * 8 + h]);
        }
    }
}

// ============================================================================
// residual + LayerNorm.  Optionally also writes half copy.
// ============================================================================
template <bool WH>
__global__ __launch_bounds__(256) void k_resln(
    const float* __restrict__ ain, const float* __restrict__ bin,
    const float* __restrict__ g, const float* __restrict__ be,
    float* __restrict__ o, __half* __restrict__ oh)
{
    const int tid = threadIdx.x;
    const int tok0 = blockIdx.x * 32;
    const int w = tid >> 5, lane = tid & 31;
#pragma unroll
    for (int rr = 0; rr < 4; rr++) {
        int row = w * 4 + rr;
        size_t rb = (size_t)(tok0 + row) * D_;
        float vals[8];
        float sum = 0.f, sq = 0.f;
#pragma unroll
        for (int i = 0; i < 8; i++) {
            float v = ain[rb + lane + i * 32] + bin[rb + lane + i * 32];
            vals[i] = v; sum += v; sq += v * v;
        }
#pragma unroll
        for (int off = 16; off > 0; off >>= 1) {
            sum += __shfl_xor_sync(0xffffffffu, sum, off);
            sq  += __shfl_xor_sync(0xffffffffu, sq,  off);
        }
        float mu  = sum * (1.f / 256.f);
        float var = sq * (1.f / 256.f) - mu * mu;
        float rs  = rsqrtf(var + 1e-5f);
#pragma unroll
        for (int i = 0; i < 8; i++) {
            int col = lane + i * 32;
            float v = (vals[i] - mu) * rs * g[col] + be[col];
            o[rb + col] = v;
            if (WH) oh[rb + col] = __float2half(v);
        }
    }
}

// ============================================================================
extern "C" void kernel_launch(void* const* d_in, const int* in_sizes, int n_in,
                              void* d_out, int out_size)
{
    const float* x    = (const float*)d_in[0];
    const float* Wq   = (const float*)d_in[1];
    const float* bq   = (const float*)d_in[2];
    const float* Wk   = (const float*)d_in[3];
    const float* bk   = (const float*)d_in[4];
    const float* Wv   = (const float*)d_in[5];
    const float* bv   = (const float*)d_in[6];
    const float* Wo   = (const float*)d_in[7];
    const float* bo   = (const float*)d_in[8];
    const float* W1   = (const float*)d_in[9];
    const float* b1   = (const float*)d_in[10];
    const float* W2   = (const float*)d_in[11];
    const float* b2   = (const float*)d_in[12];
    const float* ln1g = (const float*)d_in[13];
    const float* ln1b = (const float*)d_in[14];
    const float* ln2g = (const float*)d_in[15];
    const float* ln2b = (const float*)d_in[16];
    float* out = (float*)d_out;

    __half *xh, *qkvh, *ah, *x1h, *hh, *wqkvT, *woT, *w1T, *w2T;
    float *y, *x1, *bqkv;
    cudaGetSymbolAddress((void**)&xh,    g_xh);
    cudaGetSymbolAddress((void**)&qkvh,  g_qkvh);
    cudaGetSymbolAddress((void**)&ah,    g_ah);
    cudaGetSymbolAddress((void**)&y,     g_y);
    cudaGetSymbolAddress((void**)&x1,    g_x1);
    cudaGetSymbolAddress((void**)&x1h,   g_x1h);
    cudaGetSymbolAddress((void**)&hh,    g_hh);
    cudaGetSymbolAddress((void**)&wqkvT, g_wqkvT);
    cudaGetSymbolAddress((void**)&woT,   g_woT);
    cudaGetSymbolAddress((void**)&w1T,   g_w1T);
    cudaGetSymbolAddress((void**)&w2T,   g_w2T);
    cudaGetSymbolAddress((void**)&bqkv,  g_bqkv);

    const int GSM = 73728;   // 3-stage pipeline buffers
    cudaFuncSetAttribute((k_gemm<0,0>), cudaFuncAttributeMaxDynamicSharedMemorySize, GSM);
    cudaFuncSetAttribute((k_gemm<2,1>), cudaFuncAttributeMaxDynamicSharedMemorySize, GSM);
    cudaFuncSetAttribute((k_gemm<3,1>), cudaFuncAttributeMaxDynamicSharedMemorySize, GSM);
    cudaFuncSetAttribute(k_attnread, cudaFuncAttributeMaxDynamicSharedMemorySize, 67584);

    k_cvtx<<<MTOK * D_ / 4 / 512, 512>>>(x);
    k_catb<<<1, 256>>>(bq, bk, bv);

    dim3 trb(32, 8);
    k_tr<<<dim3(8, 8),  trb>>>(Wq, wqkvT,             D_, D_);
    k_tr<<<dim3(8, 8),  trb>>>(Wk, wqkvT + 256 * D_,  D_, D_);
    k_tr<<<dim3(8, 8),  trb>>>(Wv, wqkvT + 512 * D_,  D_, D_);
    k_tr<<<dim3(8, 8),  trb>>>(Wo, woT, D_, D_);
    k_tr<<<dim3(32, 8), trb>>>(W1, w1T, D_, FF_);
    k_tr<<<dim3(8, 32), trb>>>(W2, w2T, FF_, D_);

    // merged QKV projection (phi fused for q,k cols), half out
    k_gemm<3,1><<<dim3(6, 512), 256, GSM>>>(xh, wqkvT, bqkv, qkvh, D_, 768);

    k_kvred<<<dim3(32, NCH), 256>>>();
    k_kvfin<<<32, 256>>>();
    k_attnread<<<MTOK / 32, 256, 67584>>>(ah);

    // Wo projection + residual/LN1
    k_gemm<0,0><<<dim3(2, 512), 256, GSM>>>(ah, woT, bo, y, D_, D_);
    k_resln<true><<<MTOK / 32, 256>>>(x, y, ln1g, ln1b, x1, x1h);

    // FFN
    k_gemm<2,1><<<dim3(8, 512), 256, GSM>>>(x1h, w1T, b1, hh, D_, FF_);
    k_gemm<0,0><<<dim3(2, 512), 256, GSM>>>(hh, w2T, b2, y, FF_, D_);
    k_resln<false><<<MTOK / 32, 256>>>(x1, y, ln2g, ln2b, out, nullptr);
}

// round 8
// speedup vs baseline: 4.9629x; 1.0290x over previous
#include <cuda_runtime.h>
#include <cuda_fp16.h>
#include <math.h>
#include <stdint.h>

#define B_    4
#define L_    16384
#define D_    256
#define H_    8
#define DH_   32
#define FF_   1024
#define MTOK  65536
#define NCH   16
#define CHTOK 1024

// ---------------- scratch ----------------
__device__ __half g_xh  [MTOK * D_];     // x as half
__device__ __half g_qkvh[MTOK * 768];    // q|k|v per token (half)
__device__ __half g_ah  [MTOK * D_];     // attn readout (half)
__device__ float  g_x1  [MTOK * D_];     // LN1 output (f32, residual for LN2)
__device__ __half g_x1h [MTOK * D_];     // LN1 output (half, FFN1 A)
__device__ __half g_hh  [MTOK * FF_];    // ffn hidden (half)
__device__ float  g_kvpart[NCH * 32 * 1024];
__device__ float  g_kspart[NCH * 32 * 32];
__device__ float  g_kv[32 * 1024];
__device__ float  g_ksum[32 * 32];
// transposed weights [N,K] row-major, half
__device__ __half g_wqkvT[768 * D_];
__device__ __half g_woT[D_ * D_];
__device__ __half g_w1T[FF_ * D_];
__device__ __half g_w2T[D_ * FF_];
__device__ float  g_bqkv[768];

// ---------------- helpers ----------------
__device__ __forceinline__ uint32_t smem_u32(const void* p) {
    uint32_t a;
    asm("{ .reg .u64 t; cvta.to.shared.u64 t, %1; cvt.u32.u64 %0, t; }" : "=r"(a) : "l"(p));
    return a;
}
__device__ __forceinline__ void cp16(uint32_t dst, const void* src) {
    asm volatile("cp.async.cg.shared.global [%0], [%1], 16;" :: "r"(dst), "l"(src));
}
__device__ __forceinline__ void mma16(float* c, uint32_t a0, uint32_t a1,
                                      uint32_t a2, uint32_t a3,
                                      uint32_t b0, uint32_t b1) {
    asm volatile("mma.sync.aligned.m16n8k16.row.col.f32.f16.f16.f32 "
        "{%0,%1,%2,%3}, {%4,%5,%6,%7}, {%8,%9}, {%0,%1,%2,%3};"
        : "+f"(c[0]), "+f"(c[1]), "+f"(c[2]), "+f"(c[3])
        : "r"(a0), "r"(a1), "r"(a2), "r"(a3), "r"(b0), "r"(b1));
}

// ============================================================================
// x -> half copy
// ============================================================================
__global__ __launch_bounds__(512) void k_cvtx(const float* __restrict__ x)
{
    int i = blockIdx.x * 512 + threadIdx.x;       // one float4 each
    float4 v = *(const float4*)&x[(size_t)i * 4];
    __half2 h0 = __floats2half2_rn(v.x, v.y);
    __half2 h1 = __floats2half2_rn(v.z, v.w);
    *(uint2*)&g_xh[(size_t)i * 4] = make_uint2(*(uint32_t*)&h0, *(uint32_t*)&h1);
}

// ============================================================================
// ALL weight transposes + bias concat in ONE launch.
// blocks: [0,64) Wq | [64,128) Wk | [128,192) Wv | [192,256) Wo
//         [256,512) W1 | [512,768) W2 | 768 catb
// ============================================================================
__global__ void k_trall(const float* __restrict__ Wq, const float* __restrict__ Wk,
                        const float* __restrict__ Wv, const float* __restrict__ Wo,
                        const float* __restrict__ W1, const float* __restrict__ W2,
                        const float* __restrict__ bq, const float* __restrict__ bk,
                        const float* __restrict__ bv)
{
    const int bid = blockIdx.x;
    if (bid == 768) {
        int t = threadIdx.y * 32 + threadIdx.x;
        g_bqkv[t] = bq[t]; g_bqkv[256 + t] = bk[t]; g_bqkv[512 + t] = bv[t];
        return;
    }
    const float* W; __half* Wt; int K, N, idx;
    if (bid < 256) {                 // 256x256 weights
        idx = bid & 63; K = D_; N = D_;
        int sel = bid >> 6;
        W  = (sel == 0) ? Wq : (sel == 1) ? Wk : (sel == 2) ? Wv : Wo;
        Wt = (sel == 0) ? g_wqkvT : (sel == 1) ? g_wqkvT + 256 * D_
           : (sel == 2) ? g_wqkvT + 512 * D_ : g_woT;
    } else if (bid < 512) {          // W1 [256,1024]
        idx = bid - 256; K = D_; N = FF_; W = W1; Wt = g_w1T;
    } else {                         // W2 [1024,256]
        idx = bid - 512; K = FF_; N = D_; W = W2; Wt = g_w2T;
    }
    const int xt = N >> 5;           // x-tiles
    const int n0 = (idx % xt) * 32, k0 = (idx / xt) * 32;

    __shared__ float t[32][33];
    int x = threadIdx.x, y = threadIdx.y;
    for (int i = y; i < 32; i += 8) t[i][x] = W[(size_t)(k0 + i) * N + n0 + x];
    __syncthreads();
    for (int i = y; i < 32; i += 8)
        Wt[(size_t)(n0 + i) * K + k0 + x] = __float2half(t[x][i]);
}

// ============================================================================
// fp16 mma.sync GEMM (BN=128, 256 thr, 3-stage): QKV / FFN1.
// ACT: 2 relu | 3 phi if n0<512 (merged QKV).  Output half.
// ============================================================================
__device__ __forceinline__ void stage256(const __half* __restrict__ Ap,
                                         const __half* __restrict__ Bp,
                                         int K, uint32_t sa, uint32_t sb, int tid)
{
#pragma unroll
    for (int t = 0; t < 2; t++) {
        int i = tid + t * 256;
        int row = i >> 2, c = i & 3;
        cp16(sa + row * 96 + c * 16, Ap + (size_t)row * K + c * 8);
    }
#pragma unroll
    for (int t = 0; t < 2; t++) {
        int i = tid + t * 256;
        int row = i >> 2, c = i & 3;
        cp16(sb + row * 96 + c * 16, Bp + (size_t)row * K + c * 8);
    }
}

template <int ACT>
__global__ __launch_bounds__(256, 2) void k_gemm(
    const __half* __restrict__ A, const __half* __restrict__ Bt,
    const float* __restrict__ bias, __half* __restrict__ Out,
    int K, int Nout)
{
    extern __shared__ __half smh[];
    const int tid  = threadIdx.x;
    const int wid  = tid >> 5;
    const int lane = tid & 31;
    const int g = lane >> 2, t = lane & 3;
    const int wm = wid & 3, wn = wid >> 2;
    const int m0 = blockIdx.y * 128;
    const int n0 = blockIdx.x * 128;
    const int NC = K >> 5;

    uint32_t uA[3], uB[3];
#pragma unroll
    for (int s = 0; s < 3; s++) {
        uA[s] = smem_u32(smh + s * 6144);
        uB[s] = smem_u32(smh + 18432 + s * 6144);
    }

    float c[2][8][4] = {};
    const __half* Abase = A + (size_t)m0 * K;
    const __half* Bbase = Bt + (size_t)n0 * K;

    stage256(Abase, Bbase, K, uA[0], uB[0], tid);
    asm volatile("cp.async.commit_group;");
    stage256(Abase + 32, Bbase + 32, K, uA[1], uB[1], tid);
    asm volatile("cp.async.commit_group;");

    for (int cc = 0; cc < NC; cc++) {
        if (cc + 1 < NC) asm volatile("cp.async.wait_group 1;");
        else             asm volatile("cp.async.wait_group 0;");
        __syncthreads();
        if (cc + 2 < NC) {
            const int bs = (cc + 2) % 3;
            stage256(Abase + (cc + 2) * 32, Bbase + (cc + 2) * 32, K, uA[bs], uB[bs], tid);
            asm volatile("cp.async.commit_group;");
        }
        const int cur = cc % 3;
        const __half* a_s = smh + cur * 6144;
        const __half* b_s = smh + 18432 + cur * 6144;
#pragma unroll
        for (int s = 0; s < 2; s++) {
            uint2 va[2][2];
#pragma unroll
            for (int i = 0; i < 2; i++) {
                const int rb = (2 * wm + i) * 16;
                va[i][0] = *(const uint2*)&a_s[(rb + g)     * 48 + s * 16 + 4 * t];
                va[i][1] = *(const uint2*)&a_s[(rb + g + 8) * 48 + s * 16 + 4 * t];
            }
            uint2 vb[8];
#pragma unroll
            for (int j = 0; j < 8; j++) {
                const int n = (wn * 8 + j) * 8 + g;
                vb[j] = *(const uint2*)&b_s[n * 48 + s * 16 + 4 * t];
            }
#pragma unroll
            for (int i = 0; i < 2; i++)
#pragma unroll
                for (int j = 0; j < 8; j++)
                    mma16(c[i][j], va[i][0].x, va[i][1].x, va[i][0].y, va[i][1].y,
                          vb[j].x, vb[j].y);
        }
    }

    const bool do_phi = (ACT == 3) && (n0 < 512);
#pragma unroll
    for (int j = 0; j < 8; j++) {
        const int col = n0 + (wn * 8 + j) * 8 + t * 2;
        const float b0 = __ldg(&bias[col]);
        const float b1 = __ldg(&bias[col + 1]);
#pragma unroll
        for (int i = 0; i < 2; i++) {
            const int r0 = m0 + (2 * wm + i) * 16 + g;
            float v0 = c[i][j][0] + b0, v1 = c[i][j][1] + b1;
            float v2 = c[i][j][2] + b0, v3 = c[i][j][3] + b1;
            if (do_phi) {
                v0 = (v0 > 0.f) ? (v0 + 1.f) : expf(v0);
                v1 = (v1 > 0.f) ? (v1 + 1.f) : expf(v1);
                v2 = (v2 > 0.f) ? (v2 + 1.f) : expf(v2);
                v3 = (v3 > 0.f) ? (v3 + 1.f) : expf(v3);
            }
            if (ACT == 2) {
                v0 = fmaxf(v0, 0.f); v1 = fmaxf(v1, 0.f);
                v2 = fmaxf(v2, 0.f); v3 = fmaxf(v3, 0.f);
            }
            __half2 h0 = __floats2half2_rn(v0, v1);
            __half2 h1 = __floats2half2_rn(v2, v3);
            *(__half2*)&Out[(size_t)r0 * Nout + col]       = h0;
            *(__half2*)&Out[(size_t)(r0 + 8) * Nout + col] = h1;
        }
    }
}

// ============================================================================
// fp16 GEMM (BN=256, 512 thr, 3-stage) + bias + residual + LayerNorm fused.
// FINAL=0: writes o (f32) and oh (half).  FINAL=1: writes o (f32) only.
// warp grid 4m x 4n, warp tile 32x64 (same per-warp shape as k_gemm).
// epilogue: c+bias -> smem f32 (pitch 264), then warp-per-row LN with
// coalesced residual reads.
// ============================================================================
#define LNPITCH 264

template <int FINAL>
__global__ __launch_bounds__(512, 1) void k_gemm_ln(
    const __half* __restrict__ A, const __half* __restrict__ Bt,
    const float* __restrict__ bias, const float* __restrict__ res,
    const float* __restrict__ lg, const float* __restrict__ lb,
    float* __restrict__ o, __half* __restrict__ oh, int K)
{
    extern __shared__ __half smh[];
    const int tid  = threadIdx.x;
    const int wid  = tid >> 5;
    const int lane = tid & 31;
    const int g = lane >> 2, t = lane & 3;
    const int wm = wid & 3, wn = wid >> 2;
    const int m0 = blockIdx.x * 128;
    const int NC = K >> 5;

    // A stages: 128x48 halves (6144) at s*6144; B: 256x48 (12288) at 18432+s*12288
    uint32_t uA[3], uB[3];
#pragma unroll
    for (int s = 0; s < 3; s++) {
        uA[s] = smem_u32(smh + s * 6144);
        uB[s] = smem_u32(smh + 18432 + s * 12288);
    }

    float c[2][8][4] = {};
    const __half* Abase = A + (size_t)m0 * K;

    // staging with 512 threads
    auto stage512 = [&](int chunk, int s) {
        const __half* Ap = Abase + chunk * 32;
        const __half* Bp = Bt + chunk * 32;
        {
            int row = tid >> 2, cc4 = tid & 3;
            cp16(uA[s] + row * 96 + cc4 * 16, Ap + (size_t)row * K + cc4 * 8);
        }
#pragma unroll
        for (int tt = 0; tt < 2; tt++) {
            int i = tid + tt * 512;
            int row = i >> 2, cc4 = i & 3;
            cp16(uB[s] + row * 96 + cc4 * 16, Bp + (size_t)row * K + cc4 * 8);
        }
    };

    stage512(0, 0);
    asm volatile("cp.async.commit_group;");
    stage512(1, 1);
    asm volatile("cp.async.commit_group;");

    for (int cc = 0; cc < NC; cc++) {
        if (cc + 1 < NC) asm volatile("cp.async.wait_group 1;");
        else             asm volatile("cp.async.wait_group 0;");
        __syncthreads();
        if (cc + 2 < NC) {
            stage512(cc + 2, (cc + 2) % 3);
            asm volatile("cp.async.commit_group;");
        }
        const int cur = cc % 3;
        const __half* a_s = smh + cur * 6144;
        const __half* b_s = smh + 18432 + cur * 12288;
#pragma unroll
        for (int s = 0; s < 2; s++) {
            uint2 va[2][2];
#pragma unroll
            for (int i = 0; i < 2; i++) {
                const int rb = (2 * wm + i) * 16;
                va[i][0] = *(const uint2*)&a_s[(rb + g)     * 48 + s * 16 + 4 * t];
                va[i][1] = *(const uint2*)&a_s[(rb + g + 8) * 48 + s * 16 + 4 * t];
            }
            uint2 vb[8];
#pragma unroll
            for (int j = 0; j < 8; j++) {
                const int n = (wn * 8 + j) * 8 + g;   // wn covers 64-col span
                vb[j] = *(const uint2*)&b_s[(wn * 64 + j * 8 + g) * 48 + s * 16 + 4 * t];
                (void)n;
            }
#pragma unroll
            for (int i = 0; i < 2; i++)
#pragma unroll
                for (int j = 0; j < 8; j++)
                    mma16(c[i][j], va[i][0].x, va[i][1].x, va[i][0].y, va[i][1].y,
                          vb[j].x, vb[j].y);
        }
    }
    __syncthreads();   // retire all frag readers before smem reuse

    // ---- epilogue: c + bias -> smem f32 ----
    float* se = (float*)smh;   // 128 x LNPITCH floats
#pragma unroll
    for (int j = 0; j < 8; j++) {
        const int col = wn * 64 + j * 8 + t * 2;
        const float b0 = __ldg(&bias[col]);
        const float b1 = __ldg(&bias[col + 1]);
#pragma unroll
        for (int i = 0; i < 2; i++) {
            const int r = (2 * wm + i) * 16 + g;
            *(float2*)&se[r * LNPITCH + col] = make_float2(c[i][j][0] + b0, c[i][j][1] + b1);
            *(float2*)&se[(r + 8) * LNPITCH + col] = make_float2(c[i][j][2] + b0, c[i][j][3] + b1);
        }
    }
    __syncthreads();

    // ---- LN: warp w handles rows w*8 .. w*8+7 ----
#pragma unroll
    for (int rr = 0; rr < 8; rr++) {
        const int row = wid * 8 + rr;
        const size_t rb = (size_t)(m0 + row) * D_;
        float vals[8];
        float sum = 0.f, sq = 0.f;
#pragma unroll
        for (int i = 0; i < 8; i++) {
            float v = se[row * LNPITCH + lane + i * 32] + res[rb + lane + i * 32];
            vals[i] = v; sum += v; sq += v * v;
        }
#pragma unroll
        for (int off = 16; off > 0; off >>= 1) {
            sum += __shfl_xor_sync(0xffffffffu, sum, off);
            sq  += __shfl_xor_sync(0xffffffffu, sq,  off);
        }
        float mu  = sum * (1.f / 256.f);
        float var = sq * (1.f / 256.f) - mu * mu;
        float rs  = rsqrtf(var + 1e-5f);
#pragma unroll
        for (int i = 0; i < 8; i++) {
            const int col = lane + i * 32;
            float v = (vals[i] - mu) * rs * lg[col] + lb[col];
            o[rb + col] = v;
            if (!FINAL) oh[rb + col] = __float2half(v);
        }
    }
}

// ============================================================================
// kv reduction (reads k,v slices of g_qkvh, half)
// ============================================================================
__global__ __launch_bounds__(256) void k_kvred()
{
    __shared__ float s_part[8 * 1024];
    __shared__ float s_ksp[8 * 32];
    const int bh = blockIdx.x;
    const int b = bh >> 3, h = bh & 7;
    const int ch = blockIdx.y;
    const int w = threadIdx.x >> 5, lane = threadIdx.x & 31;

    float acc[32];
#pragma unroll
    for (int d = 0; d < 32; d++) acc[d] = 0.f;
    float ks = 0.f;
    const int t0 = ch * CHTOK;
    for (int i = w; i < CHTOK; i += 8) {
        size_t tok = (size_t)b * L_ + t0 + i;
        float kval = __half2float(g_qkvh[tok * 768 + 256 + h * DH_ + lane]);
        float vval = __half2float(g_qkvh[tok * 768 + 512 + h * DH_ + lane]);
        ks += kval;
#pragma unroll
        for (int d = 0; d < 32; d++) {
            float kd = __shfl_sync(0xffffffffu, kval, d);
            acc[d] += kd * vval;
        }
    }
#pragma unroll
    for (int d = 0; d < 32; d++) s_part[w * 1024 + d * 32 + lane] = acc[d];
    s_ksp[w * 32 + lane] = ks;
    __syncthreads();
    for (int j = threadIdx.x; j < 1024; j += 256) {
        float s = 0.f;
#pragma unroll
        for (int ww = 0; ww < 8; ww++) s += s_part[ww * 1024 + j];
        g_kvpart[((size_t)ch * 32 + bh) * 1024 + j] = s;
    }
    if (threadIdx.x < 32) {
        float s = 0.f;
#pragma unroll
        for (int ww = 0; ww < 8; ww++) s += s_ksp[ww * 32 + threadIdx.x];
        g_kspart[(ch * 32 + bh) * 32 + threadIdx.x] = s;
    }
}

__global__ __launch_bounds__(256) void k_kvfin()
{
    const int bh = blockIdx.x;
    for (int j = threadIdx.x; j < 1024; j += 256) {
        float s = 0.f;
#pragma unroll
        for (int c = 0; c < NCH; c++) s += g_kvpart[((size_t)c * 32 + bh) * 1024 + j];
        g_kv[bh * 1024 + j] = s;
    }
    if (threadIdx.x < 32) {
        float s = 0.f;
#pragma unroll
        for (int c = 0; c < NCH; c++) s += g_kspart[(c * 32 + bh) * 32 + threadIdx.x];
        g_ksum[bh * 32 + threadIdx.x] = s;
    }
}

// ============================================================================
// attention readout (q slice of g_qkvh, half); output half
// ============================================================================
__global__ __launch_bounds__(256) void k_attnread(__half* __restrict__ outa)
{
    extern __shared__ float smr[];
    float* s_kv = smr;          // 8192
    float* s_ks = smr + 8192;   // 256
    float* s_z  = smr + 8448;   // 256
    float* s_q  = smr + 8704;   // 8192

    const int tid  = threadIdx.x;
    const int tok0 = blockIdx.x * 32;
    const int b    = tok0 >> 14;

    for (int i = tid; i < 2048; i += 256)
        *(float4*)&s_kv[i * 4] = *(const float4*)&g_kv[b * 8192 + i * 4];
    if (tid < 64)
        *(float4*)&s_ks[tid * 4] = *(const float4*)&g_ksum[b * 256 + tid * 4];
    for (int i = tid; i < 2048; i += 256) {
        int row = i >> 6, c = i & 63;
        uint2 u = *(const uint2*)&g_qkvh[(size_t)(tok0 + row) * 768 + c * 4];
        float2 f0 = __half22float2(*(__half2*)&u.x);
        float2 f1 = __half22float2(*(__half2*)&u.y);
        *(float4*)&s_q[row * 256 + c * 4] = make_float4(f0.x, f0.y, f1.x, f1.y);
    }
    __syncthreads();

    {
        int r = tid & 31, h = tid >> 5;
        float s = 0.f;
#pragma unroll
        for (int d4 = 0; d4 < 8; d4++) {
            float4 q4 = *(float4*)&s_q[r * 256 + h * 32 + d4 * 4];
            float4 k4 = *(float4*)&s_ks[h * 32 + d4 * 4];
            s += q4.x * k4.x + q4.y * k4.y + q4.z * k4.z + q4.w * k4.w;
        }
        s_z[r * 8 + h] = 1.f / (s + 1e-6f);
    }
    __syncthreads();

    {
        int h = tid >> 5, e = tid & 31;
        float kvc[32];
#pragma unroll
        for (int d = 0; d < 32; d++) kvc[d] = s_kv[(h * 32 + d) * 32 + e];
        for (int r = 0; r < 32; r++) {
            float acc = 0.f;
#pragma unroll
            for (int d4 = 0; d4 < 8; d4++) {
                float4 q4 = *(float4*)&s_q[r * 256 + h * 32 + d4 * 4];
                acc += q4.x * kvc[d4 * 4] + q4.y * kvc[d4 * 4 + 1]
                     + q4.z * kvc[d4 * 4 + 2] + q4.w * kvc[d4 * 4 + 3];
            }
            outa[(size_t)(tok0 + r) * D_ + tid] = __float2half(acc * s_z[r * 8 + h]);
        }
    }
}

// ============================================================================
extern "C" void kernel_launch(void* const* d_in, const int* in_sizes, int n_in,
                              void* d_out, int out_size)
{
    const float* x    = (const float*)d_in[0];
    const float* Wq   = (const float*)d_in[1];
    const float* bq   = (const float*)d_in[2];
    const float* Wk   = (const float*)d_in[3];
    const float* bk   = (const float*)d_in[4];
    const float* Wv   = (const float*)d_in[5];
    const float* bv   = (const float*)d_in[6];
    const float* Wo   = (const float*)d_in[7];
    const float* bo   = (const float*)d_in[8];
    const float* W1   = (const float*)d_in[9];
    const float* b1   = (const float*)d_in[10];
    const float* W2   = (const float*)d_in[11];
    const float* b2   = (const float*)d_in[12];
    const float* ln1g = (const float*)d_in[13];
    const float* ln1b = (const float*)d_in[14];
    const float* ln2g = (const float*)d_in[15];
    const float* ln2b = (const float*)d_in[16];
    float* out = (float*)d_out;

    __half *xh, *qkvh, *ah, *x1h, *hh, *wqkvT, *woT, *w1T, *w2T;
    float *x1, *bqkv;
    cudaGetSymbolAddress((void**)&xh,    g_xh);
    cudaGetSymbolAddress((void**)&qkvh,  g_qkvh);
    cudaGetSymbolAddress((void**)&ah,    g_ah);
    cudaGetSymbolAddress((void**)&x1,    g_x1);
    cudaGetSymbolAddress((void**)&x1h,   g_x1h);
    cudaGetSymbolAddress((void**)&hh,    g_hh);
    cudaGetSymbolAddress((void**)&wqkvT, g_wqkvT);
    cudaGetSymbolAddress((void**)&woT,   g_woT);
    cudaGetSymbolAddress((void**)&w1T,   g_w1T);
    cudaGetSymbolAddress((void**)&w2T,   g_w2T);
    cudaGetSymbolAddress((void**)&bqkv,  g_bqkv);

    const int GSM   = 73728;                      // 256-thr GEMM, 3 stages
    const int GSMLN = 128 * LNPITCH * 4;          // 135168: max(mainloop 110592, epi)
    cudaFuncSetAttribute((k_gemm<2>), cudaFuncAttributeMaxDynamicSharedMemorySize, GSM);
    cudaFuncSetAttribute((k_gemm<3>), cudaFuncAttributeMaxDynamicSharedMemorySize, GSM);
    cudaFuncSetAttribute((k_gemm_ln<0>), cudaFuncAttributeMaxDynamicSharedMemorySize, GSMLN);
    cudaFuncSetAttribute((k_gemm_ln<1>), cudaFuncAttributeMaxDynamicSharedMemorySize, GSMLN);
    cudaFuncSetAttribute(k_attnread, cudaFuncAttributeMaxDynamicSharedMemorySize, 67584);

    k_cvtx<<<MTOK * D_ / 4 / 512, 512>>>(x);
    k_trall<<<769, dim3(32, 8)>>>(Wq, Wk, Wv, Wo, W1, W2, bq, bk, bv);

    // merged QKV projection (phi fused for q,k cols), half out
    k_gemm<3><<<dim3(6, 512), 256, GSM>>>(xh, wqkvT, bqkv, qkvh, D_, 768);

    k_kvred<<<dim3(32, NCH), 256>>>();
    k_kvfin<<<32, 256>>>();
    k_attnread<<<MTOK / 32, 256, 67584>>>(ah);

    // Wo projection + residual + LN1 (fused) -> x1 (f32) + x1h (half)
    k_gemm_ln<0><<<512, 512, GSMLN>>>(ah, woT, bo, x, ln1g, ln1b, x1, x1h, D_);

    // FFN1 (relu), half out
    k_gemm<2><<<dim3(8, 512), 256, GSM>>>(x1h, w1T, b1, hh, D_, FF_);

    // FFN2 + residual + LN2 (fused) -> out
    k_gemm_ln<1><<<512, 512, GSMLN>>>(hh, w2T, b2, x1, ln2g, ln2b, out, nullptr, FF_);
}

// round 9
// speedup vs baseline: 5.5931x; 1.1270x over previous
#include <cuda_runtime.h>
#include <cuda_fp16.h>
#include <math.h>
#include <stdint.h>

#define B_    4
#define L_    16384
#define D_    256
#define H_    8
#define DH_   32
#define FF_   1024
#define MTOK  65536
#define NCH   32
#define CHTOK 512

// ---------------- scratch ----------------
__device__ __half g_xh  [MTOK * D_];     // x as half
__device__ __half g_qkvh[MTOK * 768];    // q|k|v per token (half)
__device__ __half g_ah  [MTOK * D_];     // attn readout (half)
__device__ float  g_x1  [MTOK * D_];     // LN1 output (f32, residual for LN2)
__device__ __half g_x1h [MTOK * D_];     // LN1 output (half, FFN1 A)
__device__ __half g_hh  [MTOK * FF_];    // ffn hidden (half)
__device__ float  g_kvpart[NCH * 32 * 1024];
__device__ float  g_kspart[NCH * 32 * 32];
__device__ float  g_kv[32 * 1024];
__device__ float  g_ksum[32 * 32];
// transposed weights [N,K] row-major, half
__device__ __half g_wqkvT[768 * D_];
__device__ __half g_woT[D_ * D_];
__device__ __half g_w1T[FF_ * D_];
__device__ __half g_w2T[D_ * FF_];
__device__ float  g_bqkv[768];

// ---------------- helpers ----------------
__device__ __forceinline__ uint32_t smem_u32(const void* p) {
    uint32_t a;
    asm("{ .reg .u64 t; cvta.to.shared.u64 t, %1; cvt.u32.u64 %0, t; }" : "=r"(a) : "l"(p));
    return a;
}
__device__ __forceinline__ void cp16(uint32_t dst, const void* src) {
    asm volatile("cp.async.cg.shared.global [%0], [%1], 16;" :: "r"(dst), "l"(src));
}
__device__ __forceinline__ void mma16(float* c, uint32_t a0, uint32_t a1,
                                      uint32_t a2, uint32_t a3,
                                      uint32_t b0, uint32_t b1) {
    asm volatile("mma.sync.aligned.m16n8k16.row.col.f32.f16.f16.f32 "
        "{%0,%1,%2,%3}, {%4,%5,%6,%7}, {%8,%9}, {%0,%1,%2,%3};"
        : "+f"(c[0]), "+f"(c[1]), "+f"(c[2]), "+f"(c[3])
        : "r"(a0), "r"(a1), "r"(a2), "r"(a3), "r"(b0), "r"(b1));
}
#define LDMX4T(r, addr) \
    asm volatile("ldmatrix.sync.aligned.m8n8.x4.trans.shared.b16 {%0,%1,%2,%3}, [%4];" \
        : "=r"((r)[0]), "=r"((r)[1]), "=r"((r)[2]), "=r"((r)[3]) : "r"(addr))

// ============================================================================
// x -> half copy
// ============================================================================
__global__ __launch_bounds__(512) void k_cvtx(const float* __restrict__ x)
{
    int i = blockIdx.x * 512 + threadIdx.x;       // one float4 each
    float4 v = *(const float4*)&x[(size_t)i * 4];
    __half2 h0 = __floats2half2_rn(v.x, v.y);
    __half2 h1 = __floats2half2_rn(v.z, v.w);
    *(uint2*)&g_xh[(size_t)i * 4] = make_uint2(*(uint32_t*)&h0, *(uint32_t*)&h1);
}

// ============================================================================
// ALL weight transposes + bias concat in ONE launch.
// ============================================================================
__global__ void k_trall(const float* __restrict__ Wq, const float* __restrict__ Wk,
                        const float* __restrict__ Wv, const float* __restrict__ Wo,
                        const float* __restrict__ W1, const float* __restrict__ W2,
                        const float* __restrict__ bq, const float* __restrict__ bk,
                        const float* __restrict__ bv)
{
    const int bid = blockIdx.x;
    if (bid == 768) {
        int t = threadIdx.y * 32 + threadIdx.x;
        g_bqkv[t] = bq[t]; g_bqkv[256 + t] = bk[t]; g_bqkv[512 + t] = bv[t];
        return;
    }
    const float* W; __half* Wt; int K, N, idx;
    if (bid < 256) {
        idx = bid & 63; K = D_; N = D_;
        int sel = bid >> 6;
        W  = (sel == 0) ? Wq : (sel == 1) ? Wk : (sel == 2) ? Wv : Wo;
        Wt = (sel == 0) ? g_wqkvT : (sel == 1) ? g_wqkvT + 256 * D_
           : (sel == 2) ? g_wqkvT + 512 * D_ : g_woT;
    } else if (bid < 512) {
        idx = bid - 256; K = D_; N = FF_; W = W1; Wt = g_w1T;
    } else {
        idx = bid - 512; K = FF_; N = D_; W = W2; Wt = g_w2T;
    }
    const int xt = N >> 5;
    const int n0 = (idx % xt) * 32, k0 = (idx / xt) * 32;

    __shared__ float t[32][33];
    int x = threadIdx.x, y = threadIdx.y;
    for (int i = y; i < 32; i += 8) t[i][x] = W[(size_t)(k0 + i) * N + n0 + x];
    __syncthreads();
    for (int i = y; i < 32; i += 8)
        Wt[(size_t)(n0 + i) * K + k0 + x] = __float2half(t[x][i]);
}

// ============================================================================
// fp16 mma.sync GEMM (BN=128, 256 thr, 3-stage): QKV / FFN1.
// ============================================================================
__device__ __forceinline__ void stage256(const __half* __restrict__ Ap,
                                         const __half* __restrict__ Bp,
                                         int K, uint32_t sa, uint32_t sb, int tid)
{
#pragma unroll
    for (int t = 0; t < 2; t++) {
        int i = tid + t * 256;
        int row = i >> 2, c = i & 3;
        cp16(sa + row * 96 + c * 16, Ap + (size_t)row * K + c * 8);
    }
#pragma unroll
    for (int t = 0; t < 2; t++) {
        int i = tid + t * 256;
        int row = i >> 2, c = i & 3;
        cp16(sb + row * 96 + c * 16, Bp + (size_t)row * K + c * 8);
    }
}

template <int ACT>
__global__ __launch_bounds__(256, 2) void k_gemm(
    const __half* __restrict__ A, const __half* __restrict__ Bt,
    const float* __restrict__ bias, __half* __restrict__ Out,
    int K, int Nout)
{
    extern __shared__ __half smh[];
    const int tid  = threadIdx.x;
    const int wid  = tid >> 5;
    const int lane = tid & 31;
    const int g = lane >> 2, t = lane & 3;
    const int wm = wid & 3, wn = wid >> 2;
    const int m0 = blockIdx.y * 128;
    const int n0 = blockIdx.x * 128;
    const int NC = K >> 5;

    uint32_t uA[3], uB[3];
#pragma unroll
    for (int s = 0; s < 3; s++) {
        uA[s] = smem_u32(smh + s * 6144);
        uB[s] = smem_u32(smh + 18432 + s * 6144);
    }

    float c[2][8][4] = {};
    const __half* Abase = A + (size_t)m0 * K;
    const __half* Bbase = Bt + (size_t)n0 * K;

    stage256(Abase, Bbase, K, uA[0], uB[0], tid);
    asm volatile("cp.async.commit_group;");
    stage256(Abase + 32, Bbase + 32, K, uA[1], uB[1], tid);
    asm volatile("cp.async.commit_group;");

    for (int cc = 0; cc < NC; cc++) {
        if (cc + 1 < NC) asm volatile("cp.async.wait_group 1;");
        else             asm volatile("cp.async.wait_group 0;");
        __syncthreads();
        if (cc + 2 < NC) {
            const int bs = (cc + 2) % 3;
            stage256(Abase + (cc + 2) * 32, Bbase + (cc + 2) * 32, K, uA[bs], uB[bs], tid);
            asm volatile("cp.async.commit_group;");
        }
        const int cur = cc % 3;
        const __half* a_s = smh + cur * 6144;
        const __half* b_s = smh + 18432 + cur * 6144;
#pragma unroll
        for (int s = 0; s < 2; s++) {
            uint2 va[2][2];
#pragma unroll
            for (int i = 0; i < 2; i++) {
                const int rb = (2 * wm + i) * 16;
                va[i][0] = *(const uint2*)&a_s[(rb + g)     * 48 + s * 16 + 4 * t];
                va[i][1] = *(const uint2*)&a_s[(rb + g + 8) * 48 + s * 16 + 4 * t];
            }
            uint2 vb[8];
#pragma unroll
            for (int j = 0; j < 8; j++) {
                const int n = (wn * 8 + j) * 8 + g;
                vb[j] = *(const uint2*)&b_s[n * 48 + s * 16 + 4 * t];
            }
#pragma unroll
            for (int i = 0; i < 2; i++)
#pragma unroll
                for (int j = 0; j < 8; j++)
                    mma16(c[i][j], va[i][0].x, va[i][1].x, va[i][0].y, va[i][1].y,
                          vb[j].x, vb[j].y);
        }
    }

    const bool do_phi = (ACT == 3) && (n0 < 512);
#pragma unroll
    for (int j = 0; j < 8; j++) {
        const int col = n0 + (wn * 8 + j) * 8 + t * 2;
        const float b0 = __ldg(&bias[col]);
        const float b1 = __ldg(&bias[col + 1]);
#pragma unroll
        for (int i = 0; i < 2; i++) {
            const int r0 = m0 + (2 * wm + i) * 16 + g;
            float v0 = c[i][j][0] + b0, v1 = c[i][j][1] + b1;
            float v2 = c[i][j][2] + b0, v3 = c[i][j][3] + b1;
            if (do_phi) {
                v0 = (v0 > 0.f) ? (v0 + 1.f) : expf(v0);
                v1 = (v1 > 0.f) ? (v1 + 1.f) : expf(v1);
                v2 = (v2 > 0.f) ? (v2 + 1.f) : expf(v2);
                v3 = (v3 > 0.f) ? (v3 + 1.f) : expf(v3);
            }
            if (ACT == 2) {
                v0 = fmaxf(v0, 0.f); v1 = fmaxf(v1, 0.f);
                v2 = fmaxf(v2, 0.f); v3 = fmaxf(v3, 0.f);
            }
            __half2 h0 = __floats2half2_rn(v0, v1);
            __half2 h1 = __floats2half2_rn(v2, v3);
            *(__half2*)&Out[(size_t)r0 * Nout + col]       = h0;
            *(__half2*)&Out[(size_t)(r0 + 8) * Nout + col] = h1;
        }
    }
}

// ============================================================================
// fp16 GEMM (BN=256, 512 thr, 3-stage) + bias + residual + LayerNorm fused.
// ============================================================================
#define LNPITCH 264

template <int FINAL>
__global__ __launch_bounds__(512, 1) void k_gemm_ln(
    const __half* __restrict__ A, const __half* __restrict__ Bt,
    const float* __restrict__ bias, const float* __restrict__ res,
    const float* __restrict__ lg, const float* __restrict__ lb,
    float* __restrict__ o, __half* __restrict__ oh, int K)
{
    extern __shared__ __half smh[];
    const int tid  = threadIdx.x;
    const int wid  = tid >> 5;
    const int lane = tid & 31;
    const int g = lane >> 2, t = lane & 3;
    const int wm = wid & 3, wn = wid >> 2;
    const int m0 = blockIdx.x * 128;
    const int NC = K >> 5;

    uint32_t uA[3], uB[3];
#pragma unroll
    for (int s = 0; s < 3; s++) {
        uA[s] = smem_u32(smh + s * 6144);
        uB[s] = smem_u32(smh + 18432 + s * 12288);
    }

    float c[2][8][4] = {};
    const __half* Abase = A + (size_t)m0 * K;

    auto stage512 = [&](int chunk, int s) {
        const __half* Ap = Abase + chunk * 32;
        const __half* Bp = Bt + chunk * 32;
        {
            int row = tid >> 2, cc4 = tid & 3;
            cp16(uA[s] + row * 96 + cc4 * 16, Ap + (size_t)row * K + cc4 * 8);
        }
#pragma unroll
        for (int tt = 0; tt < 2; tt++) {
            int i = tid + tt * 512;
            int row = i >> 2, cc4 = i & 3;
            cp16(uB[s] + row * 96 + cc4 * 16, Bp + (size_t)row * K + cc4 * 8);
        }
    };

    stage512(0, 0);
    asm volatile("cp.async.commit_group;");
    stage512(1, 1);
    asm volatile("cp.async.commit_group;");

    for (int cc = 0; cc < NC; cc++) {
        if (cc + 1 < NC) asm volatile("cp.async.wait_group 1;");
        else             asm volatile("cp.async.wait_group 0;");
        __syncthreads();
        if (cc + 2 < NC) {
            stage512(cc + 2, (cc + 2) % 3);
            asm volatile("cp.async.commit_group;");
        }
        const int cur = cc % 3;
        const __half* a_s = smh + cur * 6144;
        const __half* b_s = smh + 18432 + cur * 12288;
#pragma unroll
        for (int s = 0; s < 2; s++) {
            uint2 va[2][2];
#pragma unroll
            for (int i = 0; i < 2; i++) {
                const int rb = (2 * wm + i) * 16;
                va[i][0] = *(const uint2*)&a_s[(rb + g)     * 48 + s * 16 + 4 * t];
                va[i][1] = *(const uint2*)&a_s[(rb + g + 8) * 48 + s * 16 + 4 * t];
            }
            uint2 vb[8];
#pragma unroll
            for (int j = 0; j < 8; j++)
                vb[j] = *(const uint2*)&b_s[(wn * 64 + j * 8 + g) * 48 + s * 16 + 4 * t];
#pragma unroll
            for (int i = 0; i < 2; i++)
#pragma unroll
                for (int j = 0; j < 8; j++)
                    mma16(c[i][j], va[i][0].x, va[i][1].x, va[i][0].y, va[i][1].y,
                          vb[j].x, vb[j].y);
        }
    }
    __syncthreads();

    float* se = (float*)smh;
#pragma unroll
    for (int j = 0; j < 8; j++) {
        const int col = wn * 64 + j * 8 + t * 2;
        const float b0 = __ldg(&bias[col]);
        const float b1 = __ldg(&bias[col + 1]);
#pragma unroll
        for (int i = 0; i < 2; i++) {
            const int r = (2 * wm + i) * 16 + g;
            *(float2*)&se[r * LNPITCH + col] = make_float2(c[i][j][0] + b0, c[i][j][1] + b1);
            *(float2*)&se[(r + 8) * LNPITCH + col] = make_float2(c[i][j][2] + b0, c[i][j][3] + b1);
        }
    }
    __syncthreads();

#pragma unroll
    for (int rr = 0; rr < 8; rr++) {
        const int row = wid * 8 + rr;
        const size_t rb = (size_t)(m0 + row) * D_;
        float vals[8];
        float sum = 0.f, sq = 0.f;
#pragma unroll
        for (int i = 0; i < 8; i++) {
            float v = se[row * LNPITCH + lane + i * 32] + res[rb + lane + i * 32];
            vals[i] = v; sum += v; sq += v * v;
        }
#pragma unroll
        for (int off = 16; off > 0; off >>= 1) {
            sum += __shfl_xor_sync(0xffffffffu, sum, off);
            sq  += __shfl_xor_sync(0xffffffffu, sq,  off);
        }
        float mu  = sum * (1.f / 256.f);
        float var = sq * (1.f / 256.f) - mu * mu;
        float rs  = rsqrtf(var + 1e-5f);
#pragma unroll
        for (int i = 0; i < 8; i++) {
            const int col = lane + i * 32;
            float v = (vals[i] - mu) * rs * lg[col] + lb[col];
            o[rb + col] = v;
            if (!FINAL) oh[rb + col] = __float2half(v);
        }
    }
}

// ============================================================================
// kv reduction via tensor cores.
// Per warp: 64 tokens staged into smem (pitch 40 halves), then per 16-token
// slab: ldmatrix.trans fragments (A = k^T [d x tok], B = v [tok x e]) and
// mma.m16n8k16 accumulate kv[32,32] f32.  ksum via mma with all-ones B.
// Block = 8 warps x 64 tokens = 512 tokens = 1 chunk.  Grid (32 bh, 32 ch).
// ============================================================================
__global__ __launch_bounds__(256) void k_kvred()
{
    extern __shared__ __half sred[];   // 8 warps x 5120 halves (k 64x40 | v 64x40)
    const int bh = blockIdx.x;
    const int b = bh >> 3, h = bh & 7;
    const int ch = blockIdx.y;
    const int w = threadIdx.x >> 5, lane = threadIdx.x & 31;
    const int g = lane >> 2, t = lane & 3;

    __half* k_s = sred + w * 5120;
    const uint32_t uk = smem_u32(k_s);
    const uint32_t uv = uk + 2560 * 2;   // v region, bytes

    const int tok0 = ch * CHTOK + w * 64;
    const __half* kg = g_qkvh + ((size_t)b * L_ + tok0) * 768 + 256 + h * 32;
    const __half* vg = kg + 256;

    // stage 64 tokens of k and v (4 x 16B per token each)
#pragma unroll
    for (int it = 0; it < 8; it++) {
        int i = lane + it * 32;            // 0..255
        int tok = i >> 2, c4 = i & 3;
        cp16(uk + tok * 80 + c4 * 16, kg + (size_t)tok * 768 + c4 * 8);
        cp16(uv + tok * 80 + c4 * 16, vg + (size_t)tok * 768 + c4 * 8);
    }
    asm volatile("cp.async.commit_group;");
    asm volatile("cp.async.wait_group 0;");
    __syncwarp();

    float acc[2][4][4] = {};   // [m-tile][n-block][4]
    float cs[2][4] = {};       // ksum accumulators
    const uint32_t ones2 = 0x3C003C00u;

    const int tokA = (lane & 7) + ((lane >> 4) << 3);
    const int dA   = ((lane >> 3) & 1) * 8;
    const int tokB = (lane & 7) + (((lane >> 3) & 1) << 3);
    const int eB   = ((lane >> 4) & 1) * 8;

#pragma unroll
    for (int st = 0; st < 64; st += 16) {
        uint32_t a[2][4], bb[2][4];
#pragma unroll
        for (int mi = 0; mi < 2; mi++)
            LDMX4T(a[mi], uk + (st + tokA) * 80 + (mi * 16 + dA) * 2);
#pragma unroll
        for (int np = 0; np < 2; np++)
            LDMX4T(bb[np], uv + (st + tokB) * 80 + (np * 16 + eB) * 2);
#pragma unroll
        for (int mi = 0; mi < 2; mi++) {
#pragma unroll
            for (int nb = 0; nb < 4; nb++) {
                const int np = nb >> 1, hi = nb & 1;
                mma16(acc[mi][nb], a[mi][0], a[mi][1], a[mi][2], a[mi][3],
                      bb[np][hi * 2], bb[np][hi * 2 + 1]);
            }
            mma16(cs[mi], a[mi][0], a[mi][1], a[mi][2], a[mi][3], ones2, ones2);
        }
    }
    __syncthreads();   // all warps done with staging smem -> reuse for reduction

    float* s_part = (float*)sred;            // [8][1024]
    float* s_ksp  = s_part + 8 * 1024;       // [8][32]
#pragma unroll
    for (int mi = 0; mi < 2; mi++) {
#pragma unroll
        for (int nb = 0; nb < 4; nb++) {
            const int d0 = mi * 16 + g, e0 = nb * 8 + 2 * t;
            *(float2*)&s_part[w * 1024 + d0 * 32 + e0] =
                make_float2(acc[mi][nb][0], acc[mi][nb][1]);
            *(float2*)&s_part[w * 1024 + (d0 + 8) * 32 + e0] =
                make_float2(acc[mi][nb][2], acc[mi][nb][3]);
        }
        if (t == 0) {
            s_ksp[w * 32 + mi * 16 + g]     = cs[mi][0];
            s_ksp[w * 32 + mi * 16 + g + 8] = cs[mi][2];
        }
    }
    __syncthreads();

    const int tid = threadIdx.x;
    for (int j = tid; j < 1024; j += 256) {
        float s = 0.f;
#pragma unroll
        for (int ww = 0; ww < 8; ww++) s += s_part[ww * 1024 + j];
        g_kvpart[((size_t)ch * 32 + bh) * 1024 + j] = s;
    }
    if (tid < 32) {
        float s = 0.f;
#pragma unroll
        for (int ww = 0; ww < 8; ww++) s += s_ksp[ww * 32 + tid];
        g_kspart[(ch * 32 + bh) * 32 + tid] = s;
    }
}

__global__ __launch_bounds__(256) void k_kvfin()
{
    const int bh = blockIdx.x;
    for (int j = threadIdx.x; j < 1024; j += 256) {
        float s = 0.f;
#pragma unroll
        for (int c = 0; c < NCH; c++) s += g_kvpart[((size_t)c * 32 + bh) * 1024 + j];
        g_kv[bh * 1024 + j] = s;
    }
    if (threadIdx.x < 32) {
        float s = 0.f;
#pragma unroll
        for (int c = 0; c < NCH; c++) s += g_kspart[(c * 32 + bh) * 32 + threadIdx.x];
        g_ksum[bh * 32 + threadIdx.x] = s;
    }
}

// ============================================================================
// attention readout (q slice of g_qkvh, half); output half
// ============================================================================
__global__ __launch_bounds__(256) void k_attnread(__half* __restrict__ outa)
{
    extern __shared__ float smr[];
    float* s_kv = smr;          // 8192
    float* s_ks = smr + 8192;   // 256
    float* s_z  = smr + 8448;   // 256
    float* s_q  = smr + 8704;   // 8192

    const int tid  = threadIdx.x;
    const int tok0 = blockIdx.x * 32;
    const int b    = tok0 >> 14;

    for (int i = tid; i < 2048; i += 256)
        *(float4*)&s_kv[i * 4] = *(const float4*)&g_kv[b * 8192 + i * 4];
    if (tid < 64)
        *(float4*)&s_ks[tid * 4] = *(const float4*)&g_ksum[b * 256 + tid * 4];
    for (int i = tid; i < 2048; i += 256) {
        int row = i >> 6, c = i & 63;
        uint2 u = *(const uint2*)&g_qkvh[(size_t)(tok0 + row) * 768 + c * 4];
        float2 f0 = __half22float2(*(__half2*)&u.x);
        float2 f1 = __half22float2(*(__half2*)&u.y);
        *(float4*)&s_q[row * 256 + c * 4] = make_float4(f0.x, f0.y, f1.x, f1.y);
    }
    __syncthreads();

    {
        int r = tid & 31, h = tid >> 5;
        float s = 0.f;
#pragma unroll
        for (int d4 = 0; d4 < 8; d4++) {
            float4 q4 = *(float4*)&s_q[r * 256 + h * 32 + d4 * 4];
            float4 k4 = *(float4*)&s_ks[h * 32 + d4 * 4];
            s += q4.x * k4.x + q4.y * k4.y + q4.z * k4.z + q4.w * k4.w;
        }
        s_z[r * 8 + h] = 1.f / (s + 1e-6f);
    }
    __syncthreads();

    {
        int h = tid >> 5, e = tid & 31;
        float kvc[32];
#pragma unroll
        for (int d = 0; d < 32; d++) kvc[d] = s_kv[(h * 32 + d) * 32 + e];
        for (int r = 0; r < 32; r++) {
            float acc = 0.f;
#pragma unroll
            for (int d4 = 0; d4 < 8; d4++) {
                float4 q4 = *(float4*)&s_q[r * 256 + h * 32 + d4 * 4];
                acc += q4.x * kvc[d4 * 4] + q4.y * kvc[d4 * 4 + 1]
                     + q4.z * kvc[d4 * 4 + 2] + q4.w * kvc[d4 * 4 + 3];
            }
            outa[(size_t)(tok0 + r) * D_ + tid] = __float2half(acc * s_z[r * 8 + h]);
        }
    }
}

// ============================================================================
extern "C" void kernel_launch(void* const* d_in, const int* in_sizes, int n_in,
                              void* d_out, int out_size)
{
    const float* x    = (const float*)d_in[0];
    const float* Wq   = (const float*)d_in[1];
    const float* bq   = (const float*)d_in[2];
    const float* Wk   = (const float*)d_in[3];
    const float* bk   = (const float*)d_in[4];
    const float* Wv   = (const float*)d_in[5];
    const float* bv   = (const float*)d_in[6];
    const float* Wo   = (const float*)d_in[7];
    const float* bo   = (const float*)d_in[8];
    const float* W1   = (const float*)d_in[9];
    const float* b1   = (const float*)d_in[10];
    const float* W2   = (const float*)d_in[11];
    const float* b2   = (const float*)d_in[12];
    const float* ln1g = (const float*)d_in[13];
    const float* ln1b = (const float*)d_in[14];
    const float* ln2g = (const float*)d_in[15];
    const float* ln2b = (const float*)d_in[16];
    float* out = (float*)d_out;

    __half *xh, *qkvh, *ah, *x1h, *hh, *wqkvT, *woT, *w1T, *w2T;
    float *x1, *bqkv;
    cudaGetSymbolAddress((void**)&xh,    g_xh);
    cudaGetSymbolAddress((void**)&qkvh,  g_qkvh);
    cudaGetSymbolAddress((void**)&ah,    g_ah);
    cudaGetSymbolAddress((void**)&x1,    g_x1);
    cudaGetSymbolAddress((void**)&x1h,   g_x1h);
    cudaGetSymbolAddress((void**)&hh,    g_hh);
    cudaGetSymbolAddress((void**)&wqkvT, g_wqkvT);
    cudaGetSymbolAddress((void**)&woT,   g_woT);
    cudaGetSymbolAddress((void**)&w1T,   g_w1T);
    cudaGetSymbolAddress((void**)&w2T,   g_w2T);
    cudaGetSymbolAddress((void**)&bqkv,  g_bqkv);

    const int GSM   = 73728;
    const int GSMLN = 128 * LNPITCH * 4;
    const int GSMKV = 8 * 5120 * 2;      // 81920
    cudaFuncSetAttribute((k_gemm<2>), cudaFuncAttributeMaxDynamicSharedMemorySize, GSM);
    cudaFuncSetAttribute((k_gemm<3>), cudaFuncAttributeMaxDynamicSharedMemorySize, GSM);
    cudaFuncSetAttribute((k_gemm_ln<0>), cudaFuncAttributeMaxDynamicSharedMemorySize, GSMLN);
    cudaFuncSetAttribute((k_gemm_ln<1>), cudaFuncAttributeMaxDynamicSharedMemorySize, GSMLN);
    cudaFuncSetAttribute(k_kvred, cudaFuncAttributeMaxDynamicSharedMemorySize, GSMKV);
    cudaFuncSetAttribute(k_attnread, cudaFuncAttributeMaxDynamicSharedMemorySize, 67584);

    k_cvtx<<<MTOK * D_ / 4 / 512, 512>>>(x);
    k_trall<<<769, dim3(32, 8)>>>(Wq, Wk, Wv, Wo, W1, W2, bq, bk, bv);

    // merged QKV projection (phi fused for q,k cols), half out
    k_gemm<3><<<dim3(6, 512), 256, GSM>>>(xh, wqkvT, bqkv, qkvh, D_, 768);

    k_kvred<<<dim3(32, NCH), 256, GSMKV>>>();
    k_kvfin<<<32, 256>>>();
    k_attnread<<<MTOK / 32, 256, 67584>>>(ah);

    // Wo projection + residual + LN1 (fused) -> x1 (f32) + x1h (half)
    k_gemm_ln<0><<<512, 512, GSMLN>>>(ah, woT, bo, x, ln1g, ln1b, x1, x1h, D_);

    // FFN1 (relu), half out
    k_gemm<2><<<dim3(8, 512), 256, GSM>>>(x1h, w1T, b1, hh, D_, FF_);

    // FFN2 + residual + LN2 (fused) -> out
    k_gemm_ln<1><<<512, 512, GSMLN>>>(hh, w2T, b2, x1, ln2g, ln2b, out, nullptr, FF_);
}